// round 2
// baseline (speedup 1.0000x reference)
#include <cuda_runtime.h>
#include <cstdint>

#define Nn   100000
#define Ee   1600000
#define EP   (Ee + Nn)          // edges + self loops
#define F1   128                // HEADS*HID
#define OUTF 64
#define NEG_SLOPE 0.2f

// ---------------- scratch (static device globals; no allocation) ------------
__device__ __align__(16) float  g_h1[Nn * F1];      // layer1 features (x@W1)
__device__ __align__(16) float  g_agg1[Nn * F1];    // layer1 aggregation -> elu -> layer2 input
__device__ __align__(16) float  g_h2[Nn * OUTF];    // layer2 features
__device__ float4 g_es1[Nn], g_ed1[Nn], g_den1[Nn]; // per-node scores / softmax denom (4 heads)
__device__ float  g_es2[Nn], g_ed2[Nn], g_den2[Nn];
__device__ int    g_src[Ee], g_dst[Ee];
__device__ int    g_is64;                           // edge_index stored as int64?

// ---------------- helpers ---------------------------------------------------
__device__ __forceinline__ float lrelu(float x) { return x > 0.f ? x : NEG_SLOPE * x; }

__device__ __forceinline__ void red_add_v4(float* addr, float4 v) {
    asm volatile("red.global.add.v4.f32 [%0], {%1,%2,%3,%4};"
                 :: "l"(addr), "f"(v.x), "f"(v.y), "f"(v.z), "f"(v.w) : "memory");
}

// ---------------- dtype detection + index conversion ------------------------
// If edge_index is int64 (little-endian), words at odd positions are high
// halves == 0 (all ids < 2^31). If int32, odd words are random node ids.
__global__ void k_detect(const unsigned int* __restrict__ w) {
    if (threadIdx.x == 0 && blockIdx.x == 0) {
        int all0 = 1;
        for (int i = 1; i < 2048; i += 2)
            if (w[i] != 0u) { all0 = 0; break; }
        g_is64 = all0;
    }
}

__global__ void k_convert(const int* __restrict__ ei) {
    int i = blockIdx.x * blockDim.x + threadIdx.x;
    if (i >= Ee) return;
    int s, d;
    if (g_is64) {
        s = ei[2 * i];             // low word of int64
        d = ei[2 * (Ee + i)];
    } else {
        s = ei[i];
        d = ei[Ee + i];
    }
    // defensive clamp: no-op on well-formed input, prevents any IMA otherwise
    s = min(max(s, 0), Nn - 1);
    d = min(max(d, 0), Nn - 1);
    g_src[i] = s;
    g_dst[i] = d;
}

__global__ void k_init(float* __restrict__ out, const float* __restrict__ b2) {
    int i = blockIdx.x * blockDim.x + threadIdx.x;
    if (i < Nn * F1) g_agg1[i] = 0.f;
    if (i < Nn) { g_den1[i] = make_float4(0.f, 0.f, 0.f, 0.f); g_den2[i] = 0.f; }
    if (i < Nn * OUTF) out[i] = b2[i & (OUTF - 1)];
}

// ---------------- SIMT GEMM: C[M,BN] = A[M,K] @ B[K,BN] ---------------------
template<int BM, int BN, int TM, int TN>
__global__ void gemm_k(const float* __restrict__ A, const float* __restrict__ B,
                       float* __restrict__ C, int M, int K) {
    constexpr int BK = 16;
    constexpr int TX = BN / TN;
    __shared__ float As[BK][BM];
    __shared__ float Bs[BK][BN];
    const int tid = threadIdx.x;
    const int tx = tid % TX;
    const int ty = tid / TX;
    const int row0 = blockIdx.x * BM;
    float acc[TM][TN];
#pragma unroll
    for (int m = 0; m < TM; m++)
#pragma unroll
        for (int n = 0; n < TN; n++) acc[m][n] = 0.f;

    for (int kt = 0; kt < K; kt += BK) {
        for (int i = tid; i < BM * BK; i += blockDim.x) {
            int r = i / BK, c = i % BK;
            int gr = row0 + r;
            As[c][r] = (gr < M) ? A[(size_t)gr * K + kt + c] : 0.f;
        }
        for (int i = tid; i < BK * BN; i += blockDim.x) {
            int r = i / BN, c = i % BN;
            Bs[r][c] = B[(size_t)(kt + r) * BN + c];
        }
        __syncthreads();
#pragma unroll
        for (int k = 0; k < BK; ++k) {
            float a[TM], b[TN];
#pragma unroll
            for (int m = 0; m < TM; m++) a[m] = As[k][ty * TM + m];
#pragma unroll
            for (int n = 0; n < TN; n++) b[n] = Bs[k][tx * TN + n];
#pragma unroll
            for (int m = 0; m < TM; m++)
#pragma unroll
                for (int n = 0; n < TN; n++) acc[m][n] += a[m] * b[n];
        }
        __syncthreads();
    }
#pragma unroll
    for (int m = 0; m < TM; m++) {
        int gr = row0 + ty * TM + m;
        if (gr < M) {
#pragma unroll
            for (int n = 0; n < TN; n++)
                C[(size_t)gr * BN + tx * TN + n] = acc[m][n];
        }
    }
}

// ---------------- per-node attention scores ---------------------------------
__global__ void escore1_k(const float* __restrict__ a_src, const float* __restrict__ a_dst) {
    int w = (blockIdx.x * blockDim.x + threadIdx.x) >> 5;
    int l = threadIdx.x & 31;
    if (w >= Nn) return;
    const float* row = g_h1 + (size_t)w * F1;
    float es[4], ed[4];
#pragma unroll
    for (int j = 0; j < 4; j++) {
        float v = row[j * 32 + l];
        es[j] = v * a_src[j * 32 + l];
        ed[j] = v * a_dst[j * 32 + l];
    }
#pragma unroll
    for (int o = 16; o; o >>= 1) {
#pragma unroll
        for (int j = 0; j < 4; j++) {
            es[j] += __shfl_xor_sync(0xffffffff, es[j], o);
            ed[j] += __shfl_xor_sync(0xffffffff, ed[j], o);
        }
    }
    if (l == 0) {
        g_es1[w] = make_float4(es[0], es[1], es[2], es[3]);
        g_ed1[w] = make_float4(ed[0], ed[1], ed[2], ed[3]);
    }
}

__global__ void escore2_k(const float* __restrict__ a_src, const float* __restrict__ a_dst) {
    int w = (blockIdx.x * blockDim.x + threadIdx.x) >> 5;
    int l = threadIdx.x & 31;
    if (w >= Nn) return;
    const float* row = g_h2 + (size_t)w * OUTF;
    float v0 = row[l], v1 = row[32 + l];
    float es = v0 * a_src[l] + v1 * a_src[32 + l];
    float ed = v0 * a_dst[l] + v1 * a_dst[32 + l];
#pragma unroll
    for (int o = 16; o; o >>= 1) {
        es += __shfl_xor_sync(0xffffffff, es, o);
        ed += __shfl_xor_sync(0xffffffff, ed, o);
    }
    if (l == 0) { g_es2[w] = es; g_ed2[w] = ed; }
}

// ---------------- softmax denominators (no max pass: logits are bounded) ----
__global__ void edge_den1_k() {
    int e = blockIdx.x * blockDim.x + threadIdx.x;
    if (e >= EP) return;
    int s, d;
    if (e < Ee) { s = g_src[e]; d = g_dst[e]; } else { s = d = e - Ee; }
    float4 a = g_es1[s], b = g_ed1[d];
    float4 v;
    v.x = __expf(lrelu(a.x + b.x));
    v.y = __expf(lrelu(a.y + b.y));
    v.z = __expf(lrelu(a.z + b.z));
    v.w = __expf(lrelu(a.w + b.w));
    red_add_v4((float*)&g_den1[d], v);
}

__global__ void edge_den2_k() {
    int e = blockIdx.x * blockDim.x + threadIdx.x;
    if (e >= EP) return;
    int s, d;
    if (e < Ee) { s = g_src[e]; d = g_dst[e]; } else { s = d = e - Ee; }
    atomicAdd(&g_den2[d], __expf(lrelu(g_es2[s] + g_ed2[d])));
}

// ---------------- weighted message aggregation ------------------------------
// layer 1: warp per edge; lane l covers cols 4l..4l+3 (head = l>>3)
__global__ void edge_msg1_k() {
    int gw = (blockIdx.x * blockDim.x + threadIdx.x) >> 5;
    int l = threadIdx.x & 31;
    if (gw >= EP) return;
    int s, d;
    if (gw < Ee) { s = g_src[gw]; d = g_dst[gw]; } else { s = d = gw - Ee; }
    int h = l >> 3;
    float le = ((const float*)&g_es1[s])[h] + ((const float*)&g_ed1[d])[h];
    float w  = __expf(lrelu(le)) / (((const float*)&g_den1[d])[h] + 1e-16f);
    float4 v = ((const float4*)(g_h1 + (size_t)s * F1))[l];
    v.x *= w; v.y *= w; v.z *= w; v.w *= w;
    red_add_v4(g_agg1 + (size_t)d * F1 + 4 * l, v);
}

// fused bias + ELU (in place; g_agg1 becomes layer-2 input)
__global__ void elu_k(const float* __restrict__ b1) {
    int i = blockIdx.x * blockDim.x + threadIdx.x;
    if (i >= Nn * F1) return;
    float t = g_agg1[i] + b1[i & (F1 - 1)];
    g_agg1[i] = t > 0.f ? t : expm1f(t);
}

// layer 2: 16 lanes per edge (2 edges per warp); lane covers cols 4l..4l+3
__global__ void edge_msg2_k(float* __restrict__ out) {
    int t = blockIdx.x * blockDim.x + threadIdx.x;
    int gw = t >> 4;
    int l = t & 15;
    if (gw >= EP) return;
    int s, d;
    if (gw < Ee) { s = g_src[gw]; d = g_dst[gw]; } else { s = d = gw - Ee; }
    float le = g_es2[s] + g_ed2[d];
    float w  = __expf(lrelu(le)) / (g_den2[d] + 1e-16f);
    float4 v = ((const float4*)(g_h2 + (size_t)s * OUTF))[l];
    v.x *= w; v.y *= w; v.z *= w; v.w *= w;
    red_add_v4(out + (size_t)d * OUTF + 4 * l, v);
}

// ---------------- launch ----------------------------------------------------
extern "C" void kernel_launch(void* const* d_in, const int* in_sizes, int n_in,
                              void* d_out, int out_size) {
    const float* x   = (const float*)d_in[0];
    const int*   ei  = (const int*)d_in[1];      // int32 or int64 — detected on device
    const float* W1  = (const float*)d_in[2];
    const float* as1 = (const float*)d_in[3];
    const float* ad1 = (const float*)d_in[4];
    const float* b1  = (const float*)d_in[5];
    const float* W2  = (const float*)d_in[6];
    const float* as2 = (const float*)d_in[7];
    const float* ad2 = (const float*)d_in[8];
    const float* b2  = (const float*)d_in[9];
    float* out = (float*)d_out;

    float *p_h1, *p_agg1, *p_h2;
    cudaGetSymbolAddress((void**)&p_h1,   g_h1);
    cudaGetSymbolAddress((void**)&p_agg1, g_agg1);
    cudaGetSymbolAddress((void**)&p_h2,   g_h2);

    k_detect<<<1, 32>>>((const unsigned int*)ei);
    k_convert<<<(Ee + 255) / 256, 256>>>(ei);
    k_init<<<(Nn * F1 + 255) / 256, 256>>>(out, b2);

    // layer 1
    gemm_k<128, 128, 8, 8><<<(Nn + 127) / 128, 256>>>(x, W1, p_h1, Nn, 128);
    escore1_k<<<(Nn * 32 + 255) / 256, 256>>>(as1, ad1);
    edge_den1_k<<<(EP + 255) / 256, 256>>>();
    edge_msg1_k<<<(EP + 7) / 8, 256>>>();
    elu_k<<<(Nn * F1 + 255) / 256, 256>>>(b1);

    // layer 2
    gemm_k<128, 64, 8, 4><<<(Nn + 127) / 128, 256>>>(p_agg1, W2, p_h2, Nn, 128);
    escore2_k<<<(Nn * 32 + 255) / 256, 256>>>(as2, ad2);
    edge_den2_k<<<(EP + 255) / 256, 256>>>();
    edge_msg2_k<<<(EP + 15) / 16, 256>>>(out);
}

// round 3
// speedup vs baseline: 1.1766x; 1.1766x over previous
#include <cuda_runtime.h>
#include <cstdint>

#define Nn   100000
#define Ee   1600000
#define EP   (Ee + Nn)          // edges + self loops
#define F1   128                // HEADS*HID
#define OUTF 64
#define NEG_SLOPE 0.2f

// ---------------- scratch (static device globals; no allocation) ------------
__device__ __align__(16) float  g_h1[Nn * F1];      // layer1 features (x@W1)
__device__ __align__(16) float  g_agg1[Nn * F1];    // layer1 unnormalized aggregation
__device__ __align__(16) float  g_h2[Nn * OUTF];    // layer2 features
__device__ __align__(16) float  g_agg2[Nn * OUTF];  // layer2 unnormalized aggregation
__device__ float4 g_es1[Nn], g_ed1[Nn], g_den1[Nn];
__device__ float  g_es2[Nn], g_ed2[Nn], g_den2[Nn];
__device__ int    g_src[Ee], g_dst[Ee];
__device__ int    g_is64;

// ---------------- helpers ---------------------------------------------------
__device__ __forceinline__ float lrelu(float x) { return x > 0.f ? x : NEG_SLOPE * x; }

__device__ __forceinline__ void red_add_v4(float* addr, float4 v) {
    asm volatile("red.global.add.v4.f32 [%0], {%1,%2,%3,%4};"
                 :: "l"(addr), "f"(v.x), "f"(v.y), "f"(v.z), "f"(v.w) : "memory");
}

// ---------------- dtype detection + index conversion ------------------------
__global__ void k_detect(const unsigned int* __restrict__ w) {
    if (threadIdx.x == 0 && blockIdx.x == 0) {
        int all0 = 1;
        for (int i = 1; i < 2048; i += 2)
            if (w[i] != 0u) { all0 = 0; break; }
        g_is64 = all0;
    }
}

__global__ void k_convert(const int* __restrict__ ei) {
    int i = blockIdx.x * blockDim.x + threadIdx.x;
    if (i >= Ee) return;
    int s, d;
    if (g_is64) { s = ei[2 * i]; d = ei[2 * (Ee + i)]; }
    else        { s = ei[i];     d = ei[Ee + i]; }
    s = min(max(s, 0), Nn - 1);
    d = min(max(d, 0), Nn - 1);
    g_src[i] = s;
    g_dst[i] = d;
}

__global__ void k_init() {
    int i = blockIdx.x * blockDim.x + threadIdx.x;
    if (i < Nn * F1) g_agg1[i] = 0.f;
    if (i < Nn * OUTF) g_agg2[i] = 0.f;
    if (i < Nn) { g_den1[i] = make_float4(0.f, 0.f, 0.f, 0.f); g_den2[i] = 0.f; }
}

// ---------------- SIMT GEMM: C[M,BN] = A[M,K] @ B[K,BN] ---------------------
template<int BM, int BN, int TM, int TN>
__global__ void __launch_bounds__(256, 2)
gemm_k(const float* __restrict__ A, const float* __restrict__ B,
       float* __restrict__ C, int M, int K) {
    constexpr int BK = 16;
    constexpr int TX = BN / TN;
    __shared__ float As[BK][BM + 1];
    __shared__ float Bs[BK][BN];
    const int tid = threadIdx.x;
    const int tx = tid % TX;
    const int ty = tid / TX;
    const int row0 = blockIdx.x * BM;
    float acc[TM][TN];
#pragma unroll
    for (int m = 0; m < TM; m++)
#pragma unroll
        for (int n = 0; n < TN; n++) acc[m][n] = 0.f;

    for (int kt = 0; kt < K; kt += BK) {
        // A tile: BM x BK, float4 loads, transposed scalar stores
#pragma unroll
        for (int j = tid; j < BM * BK / 4; j += 256) {
            int r = j >> 2;            // BK/4 = 4 float4 per row
            int cq = j & 3;
            int gr = row0 + r;
            float4 v = make_float4(0.f, 0.f, 0.f, 0.f);
            if (gr < M) v = *(const float4*)(A + (size_t)gr * K + kt + cq * 4);
            As[cq * 4 + 0][r] = v.x;
            As[cq * 4 + 1][r] = v.y;
            As[cq * 4 + 2][r] = v.z;
            As[cq * 4 + 3][r] = v.w;
        }
        // B tile: BK x BN, float4
#pragma unroll
        for (int j = tid; j < BK * BN / 4; j += 256) {
            int r = j / (BN / 4);
            int cq = j % (BN / 4);
            *(float4*)&Bs[r][cq * 4] = *(const float4*)(B + (size_t)(kt + r) * BN + cq * 4);
        }
        __syncthreads();
#pragma unroll
        for (int k = 0; k < BK; ++k) {
            float a[TM], b[TN];
#pragma unroll
            for (int m = 0; m < TM; m++) a[m] = As[k][ty * TM + m];
#pragma unroll
            for (int n = 0; n < TN; n++) b[n] = Bs[k][tx * TN + n];
#pragma unroll
            for (int m = 0; m < TM; m++)
#pragma unroll
                for (int n = 0; n < TN; n++) acc[m][n] += a[m] * b[n];
        }
        __syncthreads();
    }
#pragma unroll
    for (int m = 0; m < TM; m++) {
        int gr = row0 + ty * TM + m;
        if (gr < M) {
#pragma unroll
            for (int n = 0; n < TN; n++)
                C[(size_t)gr * BN + tx * TN + n] = acc[m][n];
        }
    }
}

// ---------------- per-node attention scores ---------------------------------
__global__ void escore1_k(const float* __restrict__ a_src, const float* __restrict__ a_dst) {
    int w = (blockIdx.x * blockDim.x + threadIdx.x) >> 5;
    int l = threadIdx.x & 31;
    if (w >= Nn) return;
    const float* row = g_h1 + (size_t)w * F1;
    float es[4], ed[4];
#pragma unroll
    for (int j = 0; j < 4; j++) {
        float v = row[j * 32 + l];
        es[j] = v * a_src[j * 32 + l];
        ed[j] = v * a_dst[j * 32 + l];
    }
#pragma unroll
    for (int o = 16; o; o >>= 1) {
#pragma unroll
        for (int j = 0; j < 4; j++) {
            es[j] += __shfl_xor_sync(0xffffffff, es[j], o);
            ed[j] += __shfl_xor_sync(0xffffffff, ed[j], o);
        }
    }
    if (l == 0) {
        g_es1[w] = make_float4(es[0], es[1], es[2], es[3]);
        g_ed1[w] = make_float4(ed[0], ed[1], ed[2], ed[3]);
    }
}

__global__ void escore2_k(const float* __restrict__ a_src, const float* __restrict__ a_dst) {
    int w = (blockIdx.x * blockDim.x + threadIdx.x) >> 5;
    int l = threadIdx.x & 31;
    if (w >= Nn) return;
    const float* row = g_h2 + (size_t)w * OUTF;
    float v0 = row[l], v1 = row[32 + l];
    float es = v0 * a_src[l] + v1 * a_src[32 + l];
    float ed = v0 * a_dst[l] + v1 * a_dst[32 + l];
#pragma unroll
    for (int o = 16; o; o >>= 1) {
        es += __shfl_xor_sync(0xffffffff, es, o);
        ed += __shfl_xor_sync(0xffffffff, ed, o);
    }
    if (l == 0) { g_es2[w] = es; g_ed2[w] = ed; }
}

// ---------------- fused message + denominator passes ------------------------
// layer 1: warp per edge; lane l covers cols 4l..4l+3 (head = l>>3).
// Accumulates UNNORMALIZED exp-weighted messages; lane h*8 also adds the
// exp weight to the per-(node,head) denominator. Division happens in elu_k.
__global__ void edge_msg1_k() {
    int gw = (blockIdx.x * blockDim.x + threadIdx.x) >> 5;
    int l = threadIdx.x & 31;
    if (gw >= EP) return;
    int s, d;
    if (gw < Ee) { s = g_src[gw]; d = g_dst[gw]; } else { s = d = gw - Ee; }
    int h = l >> 3;
    float le = ((const float*)&g_es1[s])[h] + ((const float*)&g_ed1[d])[h];
    float w  = __expf(lrelu(le));
    float4 v = ((const float4*)(g_h1 + (size_t)s * F1))[l];
    v.x *= w; v.y *= w; v.z *= w; v.w *= w;
    red_add_v4(g_agg1 + (size_t)d * F1 + 4 * l, v);
    if ((l & 7) == 0) atomicAdd(((float*)&g_den1[d]) + h, w);
}

// fused normalize + bias + ELU (in place; g_agg1 becomes layer-2 input)
__global__ void elu_k(const float* __restrict__ b1) {
    int i = blockIdx.x * blockDim.x + threadIdx.x;
    if (i >= Nn * F1) return;
    int node = i >> 7;
    int head = (i >> 5) & 3;
    float den = ((const float*)&g_den1[node])[head];
    float t = g_agg1[i] / (den + 1e-16f) + b1[i & (F1 - 1)];
    g_agg1[i] = t > 0.f ? t : expm1f(t);
}

// layer 2: 16 lanes per edge; lane covers cols 4l..4l+3. Unnormalized.
__global__ void edge_msg2_k() {
    int t = blockIdx.x * blockDim.x + threadIdx.x;
    int gw = t >> 4;
    int l = t & 15;
    if (gw >= EP) return;
    int s, d;
    if (gw < Ee) { s = g_src[gw]; d = g_dst[gw]; } else { s = d = gw - Ee; }
    float w = __expf(lrelu(g_es2[s] + g_ed2[d]));
    float4 v = ((const float4*)(g_h2 + (size_t)s * OUTF))[l];
    v.x *= w; v.y *= w; v.z *= w; v.w *= w;
    red_add_v4(g_agg2 + (size_t)d * OUTF + 4 * l, v);
    if (l == 0) atomicAdd(&g_den2[d], w);
}

// final normalize + bias -> d_out
__global__ void finalize_k(float* __restrict__ out, const float* __restrict__ b2) {
    int i = blockIdx.x * blockDim.x + threadIdx.x;
    if (i >= Nn * OUTF) return;
    int node = i >> 6;
    out[i] = g_agg2[i] / (g_den2[node] + 1e-16f) + b2[i & (OUTF - 1)];
}

// ---------------- launch ----------------------------------------------------
extern "C" void kernel_launch(void* const* d_in, const int* in_sizes, int n_in,
                              void* d_out, int out_size) {
    const float* x   = (const float*)d_in[0];
    const int*   ei  = (const int*)d_in[1];
    const float* W1  = (const float*)d_in[2];
    const float* as1 = (const float*)d_in[3];
    const float* ad1 = (const float*)d_in[4];
    const float* b1  = (const float*)d_in[5];
    const float* W2  = (const float*)d_in[6];
    const float* as2 = (const float*)d_in[7];
    const float* ad2 = (const float*)d_in[8];
    const float* b2  = (const float*)d_in[9];
    float* out = (float*)d_out;

    float *p_h1, *p_agg1, *p_h2;
    cudaGetSymbolAddress((void**)&p_h1,   g_h1);
    cudaGetSymbolAddress((void**)&p_agg1, g_agg1);
    cudaGetSymbolAddress((void**)&p_h2,   g_h2);

    k_detect<<<1, 32>>>((const unsigned int*)ei);
    k_convert<<<(Ee + 255) / 256, 256>>>(ei);
    k_init<<<(Nn * F1 + 255) / 256, 256>>>();

    // layer 1
    gemm_k<128, 128, 8, 8><<<(Nn + 127) / 128, 256>>>(x, W1, p_h1, Nn, 128);
    escore1_k<<<(Nn * 32 + 255) / 256, 256>>>(as1, ad1);
    edge_msg1_k<<<(EP + 7) / 8, 256>>>();
    elu_k<<<(Nn * F1 + 255) / 256, 256>>>(b1);

    // layer 2
    gemm_k<128, 64, 8, 4><<<(Nn + 127) / 128, 256>>>(p_agg1, W2, p_h2, Nn, 128);
    escore2_k<<<(Nn * 32 + 255) / 256, 256>>>(as2, ad2);
    edge_msg2_k<<<(EP + 15) / 16, 256>>>();
    finalize_k<<<(Nn * OUTF + 255) / 256, 256>>>(out, b2);
}

// round 4
// speedup vs baseline: 1.8957x; 1.6112x over previous
#include <cuda_runtime.h>
#include <cstdint>

#define Nn   100000
#define Ee   1600000
#define F1   128                // HEADS*HID
#define OUTF 64
#define NEG_SLOPE 0.2f
#define NB   ((Nn + 1023) / 1024)   // scan blocks

// ---------------- scratch (static device globals; no allocation) ------------
__device__ __align__(16) float  g_h1[Nn * F1];      // layer1 features (x@W1)
__device__ __align__(16) float  g_agg1[Nn * F1];    // layer1 out (post ELU) = layer2 in
__device__ __align__(16) float  g_h2[Nn * OUTF];    // layer2 features
__device__ float4 g_es1[Nn], g_ed1[Nn];
__device__ float  g_es2[Nn], g_ed2[Nn];
__device__ int    g_src[Ee], g_dst[Ee];
__device__ int    g_cnt[Nn];            // in-degree (preserved after hist)
__device__ int    g_rowptr[Nn];         // CSR row start
__device__ int    g_woff[Nn];           // fill cursor
__device__ int    g_bsum[NB], g_boff[NB];
__device__ int    g_csrc[Ee];           // CSR: src ids sorted by dst
__device__ int    g_is64;

// ---------------- helpers ---------------------------------------------------
__device__ __forceinline__ float lrelu(float x) { return x > 0.f ? x : NEG_SLOPE * x; }

// ---------------- dtype detection + index conversion ------------------------
__global__ void k_detect(const unsigned int* __restrict__ w) {
    if (threadIdx.x == 0 && blockIdx.x == 0) {
        int all0 = 1;
        for (int i = 1; i < 2048; i += 2)
            if (w[i] != 0u) { all0 = 0; break; }
        g_is64 = all0;
    }
}

__global__ void k_convert(const int* __restrict__ ei) {
    int i = blockIdx.x * blockDim.x + threadIdx.x;
    if (i < Nn) g_cnt[i] = 0;
    if (i >= Ee) return;
    int s, d;
    if (g_is64) { s = ei[2 * i]; d = ei[2 * (Ee + i)]; }
    else        { s = ei[i];     d = ei[Ee + i]; }
    s = min(max(s, 0), Nn - 1);
    d = min(max(d, 0), Nn - 1);
    g_src[i] = s;
    g_dst[i] = d;
}

// ---------------- CSR build --------------------------------------------------
__global__ void k_hist() {
    int i = blockIdx.x * blockDim.x + threadIdx.x;
    if (i < Ee) atomicAdd(&g_cnt[g_dst[i]], 1);
}

__global__ void k_scan_block() {          // NB blocks x 1024
    __shared__ int sh[1024];
    int t = threadIdx.x;
    int idx = blockIdx.x * 1024 + t;
    int v = (idx < Nn) ? g_cnt[idx] : 0;
    sh[t] = v;
    __syncthreads();
    for (int o = 1; o < 1024; o <<= 1) {
        int add = (t >= o) ? sh[t - o] : 0;
        __syncthreads();
        sh[t] += add;
        __syncthreads();
    }
    if (idx < Nn) g_rowptr[idx] = sh[t] - v;   // exclusive
    if (t == 1023) g_bsum[blockIdx.x] = sh[1023];
}

__global__ void k_scan_top() {
    if (threadIdx.x == 0 && blockIdx.x == 0) {
        int run = 0;
        for (int b = 0; b < NB; b++) { g_boff[b] = run; run += g_bsum[b]; }
    }
}

__global__ void k_scan_add() {
    int i = blockIdx.x * blockDim.x + threadIdx.x;
    if (i >= Nn) return;
    int r = g_rowptr[i] + g_boff[i >> 10];
    g_rowptr[i] = r;
    g_woff[i] = r;
}

__global__ void k_fill() {
    int i = blockIdx.x * blockDim.x + threadIdx.x;
    if (i >= Ee) return;
    int d = g_dst[i];
    int pos = atomicAdd(&g_woff[d], 1);
    g_csrc[pos] = g_src[i];
}

// ---------------- SIMT GEMM: C[M,BN] = A[M,K] @ B[K,BN] ---------------------
template<int BM, int BN, int TM, int TN>
__global__ void __launch_bounds__(256, 2)
gemm_k(const float* __restrict__ A, const float* __restrict__ B,
       float* __restrict__ C, int M, int K) {
    constexpr int BK = 16;
    constexpr int TX = BN / TN;
    __shared__ float As[BK][BM + 1];
    __shared__ float Bs[BK][BN];
    const int tid = threadIdx.x;
    const int tx = tid % TX;
    const int ty = tid / TX;
    const int row0 = blockIdx.x * BM;
    float acc[TM][TN];
#pragma unroll
    for (int m = 0; m < TM; m++)
#pragma unroll
        for (int n = 0; n < TN; n++) acc[m][n] = 0.f;

    for (int kt = 0; kt < K; kt += BK) {
#pragma unroll
        for (int j = tid; j < BM * BK / 4; j += 256) {
            int r = j >> 2;
            int cq = j & 3;
            int gr = row0 + r;
            float4 v = make_float4(0.f, 0.f, 0.f, 0.f);
            if (gr < M) v = *(const float4*)(A + (size_t)gr * K + kt + cq * 4);
            As[cq * 4 + 0][r] = v.x;
            As[cq * 4 + 1][r] = v.y;
            As[cq * 4 + 2][r] = v.z;
            As[cq * 4 + 3][r] = v.w;
        }
#pragma unroll
        for (int j = tid; j < BK * BN / 4; j += 256) {
            int r = j / (BN / 4);
            int cq = j % (BN / 4);
            *(float4*)&Bs[r][cq * 4] = *(const float4*)(B + (size_t)(kt + r) * BN + cq * 4);
        }
        __syncthreads();
#pragma unroll
        for (int k = 0; k < BK; ++k) {
            float a[TM], b[TN];
#pragma unroll
            for (int m = 0; m < TM; m++) a[m] = As[k][ty * TM + m];
#pragma unroll
            for (int n = 0; n < TN; n++) b[n] = Bs[k][tx * TN + n];
#pragma unroll
            for (int m = 0; m < TM; m++)
#pragma unroll
                for (int n = 0; n < TN; n++) acc[m][n] += a[m] * b[n];
        }
        __syncthreads();
    }
#pragma unroll
    for (int m = 0; m < TM; m++) {
        int gr = row0 + ty * TM + m;
        if (gr < M) {
#pragma unroll
            for (int n = 0; n < TN; n++)
                C[(size_t)gr * BN + tx * TN + n] = acc[m][n];
        }
    }
}

// ---------------- per-node attention scores ---------------------------------
__global__ void escore1_k(const float* __restrict__ a_src, const float* __restrict__ a_dst) {
    int w = (blockIdx.x * blockDim.x + threadIdx.x) >> 5;
    int l = threadIdx.x & 31;
    if (w >= Nn) return;
    const float* row = g_h1 + (size_t)w * F1;
    float es[4], ed[4];
#pragma unroll
    for (int j = 0; j < 4; j++) {
        float v = row[j * 32 + l];
        es[j] = v * a_src[j * 32 + l];
        ed[j] = v * a_dst[j * 32 + l];
    }
#pragma unroll
    for (int o = 16; o; o >>= 1) {
#pragma unroll
        for (int j = 0; j < 4; j++) {
            es[j] += __shfl_xor_sync(0xffffffff, es[j], o);
            ed[j] += __shfl_xor_sync(0xffffffff, ed[j], o);
        }
    }
    if (l == 0) {
        g_es1[w] = make_float4(es[0], es[1], es[2], es[3]);
        g_ed1[w] = make_float4(ed[0], ed[1], ed[2], ed[3]);
    }
}

__global__ void escore2_k(const float* __restrict__ a_src, const float* __restrict__ a_dst) {
    int w = (blockIdx.x * blockDim.x + threadIdx.x) >> 5;
    int l = threadIdx.x & 31;
    if (w >= Nn) return;
    const float* row = g_h2 + (size_t)w * OUTF;
    float v0 = row[l], v1 = row[32 + l];
    float es = v0 * a_src[l] + v1 * a_src[32 + l];
    float ed = v0 * a_dst[l] + v1 * a_dst[32 + l];
#pragma unroll
    for (int o = 16; o; o >>= 1) {
        es += __shfl_xor_sync(0xffffffff, es, o);
        ed += __shfl_xor_sync(0xffffffff, ed, o);
    }
    if (l == 0) { g_es2[w] = es; g_ed2[w] = ed; }
}

// ---------------- gather-based message passes (CSR, no atomics) --------------
// Layer 1: one warp per dst node. Lane l owns cols 4l..4l+3; head h = l>>3.
// All lanes of a head group compute identical w and den -> pure register
// accumulation, zero shuffles. Epilogue fuses normalize + bias + ELU.
__global__ void msg1_k(const float* __restrict__ b1) {
    int d = (blockIdx.x * blockDim.x + threadIdx.x) >> 5;
    int l = threadIdx.x & 31;
    if (d >= Nn) return;
    int h = l >> 3;
    const float* es = (const float*)g_es1;
    float edh = ((const float*)&g_ed1[d])[h];
    int start = g_rowptr[d];
    int cnt = g_cnt[d];

    float4 acc = make_float4(0.f, 0.f, 0.f, 0.f);
    float den = 0.f;
    // self-loop
    {
        float w = __expf(lrelu(es[4 * d + h] + edh));
        float4 v = ((const float4*)(g_h1 + (size_t)d * F1))[l];
        acc.x = w * v.x; acc.y = w * v.y; acc.z = w * v.z; acc.w = w * v.w;
        den = w;
    }
    for (int e = start; e < start + cnt; e++) {
        int s = g_csrc[e];
        float w = __expf(lrelu(es[4 * s + h] + edh));
        float4 v = ((const float4*)(g_h1 + (size_t)s * F1))[l];
        acc.x += w * v.x; acc.y += w * v.y; acc.z += w * v.z; acc.w += w * v.w;
        den += w;
    }
    float inv = 1.f / (den + 1e-16f);
    const float4 bb = ((const float4*)b1)[l];
    float4 o;
    o.x = acc.x * inv + bb.x;
    o.y = acc.y * inv + bb.y;
    o.z = acc.z * inv + bb.z;
    o.w = acc.w * inv + bb.w;
    o.x = o.x > 0.f ? o.x : expm1f(o.x);
    o.y = o.y > 0.f ? o.y : expm1f(o.y);
    o.z = o.z > 0.f ? o.z : expm1f(o.z);
    o.w = o.w > 0.f ? o.w : expm1f(o.w);
    ((float4*)(g_agg1 + (size_t)d * F1))[l] = o;
}

// Layer 2: one warp per dst node, lane l owns cols 2l, 2l+1 (single head).
// Epilogue fuses normalize + bias, writes straight to d_out.
__global__ void msg2_k(float* __restrict__ out, const float* __restrict__ b2) {
    int d = (blockIdx.x * blockDim.x + threadIdx.x) >> 5;
    int l = threadIdx.x & 31;
    if (d >= Nn) return;
    float edh = g_ed2[d];
    int start = g_rowptr[d];
    int cnt = g_cnt[d];

    float2 acc;
    float den;
    {
        float w = __expf(lrelu(g_es2[d] + edh));
        float2 v = ((const float2*)(g_h2 + (size_t)d * OUTF))[l];
        acc.x = w * v.x; acc.y = w * v.y;
        den = w;
    }
    for (int e = start; e < start + cnt; e++) {
        int s = g_csrc[e];
        float w = __expf(lrelu(g_es2[s] + edh));
        float2 v = ((const float2*)(g_h2 + (size_t)s * OUTF))[l];
        acc.x += w * v.x; acc.y += w * v.y;
        den += w;
    }
    float inv = 1.f / (den + 1e-16f);
    const float2 bb = ((const float2*)b2)[l];
    float2 o;
    o.x = acc.x * inv + bb.x;
    o.y = acc.y * inv + bb.y;
    ((float2*)(out + (size_t)d * OUTF))[l] = o;
}

// ---------------- launch ----------------------------------------------------
extern "C" void kernel_launch(void* const* d_in, const int* in_sizes, int n_in,
                              void* d_out, int out_size) {
    const float* x   = (const float*)d_in[0];
    const int*   ei  = (const int*)d_in[1];
    const float* W1  = (const float*)d_in[2];
    const float* as1 = (const float*)d_in[3];
    const float* ad1 = (const float*)d_in[4];
    const float* b1  = (const float*)d_in[5];
    const float* W2  = (const float*)d_in[6];
    const float* as2 = (const float*)d_in[7];
    const float* ad2 = (const float*)d_in[8];
    const float* b2  = (const float*)d_in[9];
    float* out = (float*)d_out;

    float *p_h1, *p_agg1, *p_h2;
    cudaGetSymbolAddress((void**)&p_h1,   g_h1);
    cudaGetSymbolAddress((void**)&p_agg1, g_agg1);
    cudaGetSymbolAddress((void**)&p_h2,   g_h2);

    // index decode + CSR build
    k_detect<<<1, 32>>>((const unsigned int*)ei);
    k_convert<<<(Ee + 255) / 256, 256>>>(ei);
    k_hist<<<(Ee + 255) / 256, 256>>>();
    k_scan_block<<<NB, 1024>>>();
    k_scan_top<<<1, 32>>>();
    k_scan_add<<<(Nn + 255) / 256, 256>>>();
    k_fill<<<(Ee + 255) / 256, 256>>>();

    // layer 1
    gemm_k<128, 128, 8, 8><<<(Nn + 127) / 128, 256>>>(x, W1, p_h1, Nn, 128);
    escore1_k<<<(Nn * 32 + 255) / 256, 256>>>(as1, ad1);
    msg1_k<<<(Nn * 32 + 255) / 256, 256>>>(b1);

    // layer 2
    gemm_k<128, 64, 8, 4><<<(Nn + 127) / 128, 256>>>(p_agg1, W2, p_h2, Nn, 128);
    escore2_k<<<(Nn * 32 + 255) / 256, 256>>>(as2, ad2);
    msg2_k<<<(Nn * 32 + 255) / 256, 256>>>(out, b2);
}

// round 5
// speedup vs baseline: 2.0365x; 1.0743x over previous
#include <cuda_runtime.h>
#include <cuda_bf16.h>
#include <cstdint>

#define Nn   100000
#define Ee   1600000
#define F1   128                // HEADS*HID
#define OUTF 64
#define NEG_SLOPE 0.2f
#define NB   ((Nn + 1023) / 1024)   // scan blocks

// ---------------- scratch (static device globals; no allocation) ------------
__device__ __align__(16) float  g_h1[Nn * F1];
__device__ __align__(16) float  g_agg1[Nn * F1];
__device__ __align__(16) float  g_h2[Nn * OUTF];
__device__ float4 g_es1[Nn], g_ed1[Nn];
__device__ float  g_es2[Nn], g_ed2[Nn];
__device__ int    g_src[Ee], g_dst[Ee];
__device__ int    g_cnt[Nn];
__device__ int    g_rowptr[Nn];
__device__ int    g_woff[Nn];
__device__ int    g_bsum[NB], g_boff[NB];
__device__ int    g_csrc[Ee];
__device__ int    g_is64;

// ---------------- helpers ---------------------------------------------------
__device__ __forceinline__ float lrelu(float x) { return x > 0.f ? x : NEG_SLOPE * x; }

__device__ __forceinline__ void mma_bf16(float c[4], uint32_t a0, uint32_t a1,
                                         uint32_t a2, uint32_t a3,
                                         uint32_t b0, uint32_t b1) {
    asm volatile("mma.sync.aligned.m16n8k16.row.col.f32.bf16.bf16.f32 "
                 "{%0,%1,%2,%3}, {%4,%5,%6,%7}, {%8,%9}, {%0,%1,%2,%3};"
                 : "+f"(c[0]), "+f"(c[1]), "+f"(c[2]), "+f"(c[3])
                 : "r"(a0), "r"(a1), "r"(a2), "r"(a3), "r"(b0), "r"(b1));
}

// ---------------- dtype detection + index conversion ------------------------
__global__ void k_detect(const unsigned int* __restrict__ w) {
    if (threadIdx.x == 0 && blockIdx.x == 0) {
        int all0 = 1;
        for (int i = 1; i < 2048; i += 2)
            if (w[i] != 0u) { all0 = 0; break; }
        g_is64 = all0;
    }
}

__global__ void k_convert(const int* __restrict__ ei) {
    int i = blockIdx.x * blockDim.x + threadIdx.x;
    if (i < Nn) g_cnt[i] = 0;
    if (i >= Ee) return;
    int s, d;
    if (g_is64) { s = ei[2 * i]; d = ei[2 * (Ee + i)]; }
    else        { s = ei[i];     d = ei[Ee + i]; }
    s = min(max(s, 0), Nn - 1);
    d = min(max(d, 0), Nn - 1);
    g_src[i] = s;
    g_dst[i] = d;
}

// ---------------- CSR build --------------------------------------------------
__global__ void k_hist() {
    int i = blockIdx.x * blockDim.x + threadIdx.x;
    if (i < Ee) atomicAdd(&g_cnt[g_dst[i]], 1);
}

__global__ void k_scan_block() {
    __shared__ int sh[1024];
    int t = threadIdx.x;
    int idx = blockIdx.x * 1024 + t;
    int v = (idx < Nn) ? g_cnt[idx] : 0;
    sh[t] = v;
    __syncthreads();
    for (int o = 1; o < 1024; o <<= 1) {
        int add = (t >= o) ? sh[t - o] : 0;
        __syncthreads();
        sh[t] += add;
        __syncthreads();
    }
    if (idx < Nn) g_rowptr[idx] = sh[t] - v;
    if (t == 1023) g_bsum[blockIdx.x] = sh[1023];
}

__global__ void k_scan_top() {
    if (threadIdx.x == 0 && blockIdx.x == 0) {
        int run = 0;
        for (int b = 0; b < NB; b++) { g_boff[b] = run; run += g_bsum[b]; }
    }
}

__global__ void k_scan_add() {
    int i = blockIdx.x * blockDim.x + threadIdx.x;
    if (i >= Nn) return;
    int r = g_rowptr[i] + g_boff[i >> 10];
    g_rowptr[i] = r;
    g_woff[i] = r;
}

__global__ void k_fill() {
    int i = blockIdx.x * blockDim.x + threadIdx.x;
    if (i >= Ee) return;
    int d = g_dst[i];
    int pos = atomicAdd(&g_woff[d], 1);
    g_csrc[pos] = g_src[i];
}

// ---------------- bf16 split-K tensor-core GEMM ------------------------------
// C[M,BN] = A[M,128] @ B[128,BN] with 3-pass bf16 split (hi*hi + hi*lo + lo*hi)
// Block: 256 thr = 8 warps; tile 128 rows x BN cols. Warp: 32 rows x BN/2 cols.
template<int BN>
__global__ void __launch_bounds__(256, 2)
gemm_tc(const float* __restrict__ A, const float* __restrict__ B,
        float* __restrict__ C, int M) {
    constexpr int K  = 128;
    constexpr int BK = 32;
    constexpr int AP = 40;             // padded row length (bf16) - conflict-free
    constexpr int NBW = BN / 16;       // n8-blocks per warp

    __shared__ __nv_bfloat16 As_hi[128 * AP], As_lo[128 * AP];
    __shared__ __nv_bfloat16 Bs_hi[BN * AP],  Bs_lo[BN * AP];

    const int tid  = threadIdx.x;
    const int w    = tid >> 5;
    const int lane = tid & 31;
    const int g    = lane >> 2;
    const int q    = lane & 3;
    const int wrow = (w >> 1) * 32;          // warp row base within tile
    const int n0w  = (w & 1) * (BN / 2);     // warp col base
    const int row0 = blockIdx.x * 128;

    float c[2][NBW][4];
#pragma unroll
    for (int m = 0; m < 2; m++)
#pragma unroll
        for (int nb = 0; nb < NBW; nb++)
#pragma unroll
            for (int j = 0; j < 4; j++) c[m][nb][j] = 0.f;

    for (int kt = 0; kt < K; kt += BK) {
        __syncthreads();
        // A tile: 128 rows x 32 k (8 float4 per row)
#pragma unroll
        for (int it = 0; it < 4; it++) {
            int i = tid + it * 256;            // 0..1023
            int row = i >> 3, kq = i & 7;
            int gr = row0 + row;
            float4 v = make_float4(0.f, 0.f, 0.f, 0.f);
            if (gr < M) v = *(const float4*)(A + (size_t)gr * K + kt + kq * 4);
            int base = row * AP + kq * 4;
            float vv[4] = {v.x, v.y, v.z, v.w};
#pragma unroll
            for (int j = 0; j < 4; j++) {
                __nv_bfloat16 hi = __float2bfloat16(vv[j]);
                As_hi[base + j] = hi;
                As_lo[base + j] = __float2bfloat16(vv[j] - __bfloat162float(hi));
            }
        }
        // B tile: 32 k x BN, stored transposed [n][k]
#pragma unroll
        for (int it = 0; it < (32 * BN / 4) / 256; it++) {
            int i = tid + it * 256;
            int k = i / (BN / 4), nq = i % (BN / 4);
            float4 v = *(const float4*)(B + (size_t)(kt + k) * BN + nq * 4);
            float vv[4] = {v.x, v.y, v.z, v.w};
#pragma unroll
            for (int j = 0; j < 4; j++) {
                __nv_bfloat16 hi = __float2bfloat16(vv[j]);
                Bs_hi[(nq * 4 + j) * AP + k] = hi;
                Bs_lo[(nq * 4 + j) * AP + k] = __float2bfloat16(vv[j] - __bfloat162float(hi));
            }
        }
        __syncthreads();

#pragma unroll
        for (int kk = 0; kk < BK; kk += 16) {
            uint32_t ahi[2][4], alo[2][4];
#pragma unroll
            for (int m = 0; m < 2; m++) {
                int rb = (wrow + m * 16 + g) * AP + kk + 2 * q;
                ahi[m][0] = *(const uint32_t*)&As_hi[rb];
                ahi[m][1] = *(const uint32_t*)&As_hi[rb + 8 * AP];
                ahi[m][2] = *(const uint32_t*)&As_hi[rb + 8];
                ahi[m][3] = *(const uint32_t*)&As_hi[rb + 8 * AP + 8];
                alo[m][0] = *(const uint32_t*)&As_lo[rb];
                alo[m][1] = *(const uint32_t*)&As_lo[rb + 8 * AP];
                alo[m][2] = *(const uint32_t*)&As_lo[rb + 8];
                alo[m][3] = *(const uint32_t*)&As_lo[rb + 8 * AP + 8];
            }
#pragma unroll
            for (int nb = 0; nb < NBW; nb++) {
                int bb = (n0w + nb * 8 + g) * AP + kk + 2 * q;
                uint32_t bh0 = *(const uint32_t*)&Bs_hi[bb];
                uint32_t bh1 = *(const uint32_t*)&Bs_hi[bb + 8];
                uint32_t bl0 = *(const uint32_t*)&Bs_lo[bb];
                uint32_t bl1 = *(const uint32_t*)&Bs_lo[bb + 8];
#pragma unroll
                for (int m = 0; m < 2; m++) {
                    mma_bf16(c[m][nb], ahi[m][0], ahi[m][1], ahi[m][2], ahi[m][3], bh0, bh1);
                    mma_bf16(c[m][nb], ahi[m][0], ahi[m][1], ahi[m][2], ahi[m][3], bl0, bl1);
                    mma_bf16(c[m][nb], alo[m][0], alo[m][1], alo[m][2], alo[m][3], bh0, bh1);
                }
            }
        }
    }

    // epilogue: c0,c1 -> (row, col..col+1); c2,c3 -> (row+8, ...)
#pragma unroll
    for (int m = 0; m < 2; m++) {
#pragma unroll
        for (int nb = 0; nb < NBW; nb++) {
            int row = row0 + wrow + m * 16 + g;
            int col = n0w + nb * 8 + 2 * q;
            if (row < M)
                *(float2*)(C + (size_t)row * BN + col) = make_float2(c[m][nb][0], c[m][nb][1]);
            if (row + 8 < M)
                *(float2*)(C + (size_t)(row + 8) * BN + col) = make_float2(c[m][nb][2], c[m][nb][3]);
        }
    }
}

// ---------------- per-node attention scores ---------------------------------
__global__ void escore1_k(const float* __restrict__ a_src, const float* __restrict__ a_dst) {
    int w = (blockIdx.x * blockDim.x + threadIdx.x) >> 5;
    int l = threadIdx.x & 31;
    if (w >= Nn) return;
    const float* row = g_h1 + (size_t)w * F1;
    float es[4], ed[4];
#pragma unroll
    for (int j = 0; j < 4; j++) {
        float v = row[j * 32 + l];
        es[j] = v * a_src[j * 32 + l];
        ed[j] = v * a_dst[j * 32 + l];
    }
#pragma unroll
    for (int o = 16; o; o >>= 1) {
#pragma unroll
        for (int j = 0; j < 4; j++) {
            es[j] += __shfl_xor_sync(0xffffffff, es[j], o);
            ed[j] += __shfl_xor_sync(0xffffffff, ed[j], o);
        }
    }
    if (l == 0) {
        g_es1[w] = make_float4(es[0], es[1], es[2], es[3]);
        g_ed1[w] = make_float4(ed[0], ed[1], ed[2], ed[3]);
    }
}

__global__ void escore2_k(const float* __restrict__ a_src, const float* __restrict__ a_dst) {
    int w = (blockIdx.x * blockDim.x + threadIdx.x) >> 5;
    int l = threadIdx.x & 31;
    if (w >= Nn) return;
    const float* row = g_h2 + (size_t)w * OUTF;
    float v0 = row[l], v1 = row[32 + l];
    float es = v0 * a_src[l] + v1 * a_src[32 + l];
    float ed = v0 * a_dst[l] + v1 * a_dst[32 + l];
#pragma unroll
    for (int o = 16; o; o >>= 1) {
        es += __shfl_xor_sync(0xffffffff, es, o);
        ed += __shfl_xor_sync(0xffffffff, ed, o);
    }
    if (l == 0) { g_es2[w] = es; g_ed2[w] = ed; }
}

// ---------------- gather-based message passes (CSR, no atomics) --------------
__global__ void msg1_k(const float* __restrict__ b1) {
    int d = (blockIdx.x * blockDim.x + threadIdx.x) >> 5;
    int l = threadIdx.x & 31;
    if (d >= Nn) return;
    int h = l >> 3;
    const float* es = (const float*)g_es1;
    float edh = ((const float*)&g_ed1[d])[h];
    int start = g_rowptr[d];
    int cnt = g_cnt[d];

    float4 acc = make_float4(0.f, 0.f, 0.f, 0.f);
    float den = 0.f;
    {
        float w = __expf(lrelu(es[4 * d + h] + edh));
        float4 v = ((const float4*)(g_h1 + (size_t)d * F1))[l];
        acc.x = w * v.x; acc.y = w * v.y; acc.z = w * v.z; acc.w = w * v.w;
        den = w;
    }
    for (int e = start; e < start + cnt; e++) {
        int s = g_csrc[e];
        float w = __expf(lrelu(es[4 * s + h] + edh));
        float4 v = ((const float4*)(g_h1 + (size_t)s * F1))[l];
        acc.x += w * v.x; acc.y += w * v.y; acc.z += w * v.z; acc.w += w * v.w;
        den += w;
    }
    float inv = 1.f / (den + 1e-16f);
    const float4 bb = ((const float4*)b1)[l];
    float4 o;
    o.x = acc.x * inv + bb.x;
    o.y = acc.y * inv + bb.y;
    o.z = acc.z * inv + bb.z;
    o.w = acc.w * inv + bb.w;
    o.x = o.x > 0.f ? o.x : expm1f(o.x);
    o.y = o.y > 0.f ? o.y : expm1f(o.y);
    o.z = o.z > 0.f ? o.z : expm1f(o.z);
    o.w = o.w > 0.f ? o.w : expm1f(o.w);
    ((float4*)(g_agg1 + (size_t)d * F1))[l] = o;
}

__global__ void msg2_k(float* __restrict__ out, const float* __restrict__ b2) {
    int d = (blockIdx.x * blockDim.x + threadIdx.x) >> 5;
    int l = threadIdx.x & 31;
    if (d >= Nn) return;
    float edh = g_ed2[d];
    int start = g_rowptr[d];
    int cnt = g_cnt[d];

    float2 acc;
    float den;
    {
        float w = __expf(lrelu(g_es2[d] + edh));
        float2 v = ((const float2*)(g_h2 + (size_t)d * OUTF))[l];
        acc.x = w * v.x; acc.y = w * v.y;
        den = w;
    }
    for (int e = start; e < start + cnt; e++) {
        int s = g_csrc[e];
        float w = __expf(lrelu(g_es2[s] + edh));
        float2 v = ((const float2*)(g_h2 + (size_t)s * OUTF))[l];
        acc.x += w * v.x; acc.y += w * v.y;
        den += w;
    }
    float inv = 1.f / (den + 1e-16f);
    const float2 bb = ((const float2*)b2)[l];
    float2 o;
    o.x = acc.x * inv + bb.x;
    o.y = acc.y * inv + bb.y;
    ((float2*)(out + (size_t)d * OUTF))[l] = o;
}

// ---------------- launch ----------------------------------------------------
extern "C" void kernel_launch(void* const* d_in, const int* in_sizes, int n_in,
                              void* d_out, int out_size) {
    const float* x   = (const float*)d_in[0];
    const int*   ei  = (const int*)d_in[1];
    const float* W1  = (const float*)d_in[2];
    const float* as1 = (const float*)d_in[3];
    const float* ad1 = (const float*)d_in[4];
    const float* b1  = (const float*)d_in[5];
    const float* W2  = (const float*)d_in[6];
    const float* as2 = (const float*)d_in[7];
    const float* ad2 = (const float*)d_in[8];
    const float* b2  = (const float*)d_in[9];
    float* out = (float*)d_out;

    float *p_h1, *p_agg1, *p_h2;
    cudaGetSymbolAddress((void**)&p_h1,   g_h1);
    cudaGetSymbolAddress((void**)&p_agg1, g_agg1);
    cudaGetSymbolAddress((void**)&p_h2,   g_h2);

    // index decode + CSR build
    k_detect<<<1, 32>>>((const unsigned int*)ei);
    k_convert<<<(Ee + 255) / 256, 256>>>(ei);
    k_hist<<<(Ee + 255) / 256, 256>>>();
    k_scan_block<<<NB, 1024>>>();
    k_scan_top<<<1, 32>>>();
    k_scan_add<<<(Nn + 255) / 256, 256>>>();
    k_fill<<<(Ee + 255) / 256, 256>>>();

    // layer 1
    gemm_tc<128><<<(Nn + 127) / 128, 256>>>(x, W1, p_h1, Nn);
    escore1_k<<<(Nn * 32 + 255) / 256, 256>>>(as1, ad1);
    msg1_k<<<(Nn * 32 + 255) / 256, 256>>>(b1);

    // layer 2
    gemm_tc<64><<<(Nn + 127) / 128, 256>>>(p_agg1, W2, p_h2, Nn);
    escore2_k<<<(Nn * 32 + 255) / 256, 256>>>(as2, ad2);
    msg2_k<<<(Nn * 32 + 255) / 256, 256>>>(out, b2);
}

// round 6
// speedup vs baseline: 2.6288x; 1.2908x over previous
#include <cuda_runtime.h>
#include <cuda_bf16.h>
#include <cstdint>

#define Nn   100000
#define Ee   1600000
#define F1   128                // HEADS*HID
#define OUTF 64
#define NEG_SLOPE 0.2f
#define NB   ((Nn + 1023) / 1024)   // scan blocks

// ---------------- scratch (static device globals; no allocation) ------------
__device__ __align__(16) float  g_h1[Nn * F1];
__device__ __align__(16) float  g_agg1[Nn * F1];
__device__ __align__(16) float  g_h2[Nn * OUTF];
__device__ float4 g_es1[Nn], g_ed1[Nn];
__device__ float  g_es2[Nn], g_ed2[Nn];
__device__ int    g_src[Ee], g_dst[Ee];
__device__ int    g_cnt[Nn];
__device__ int    g_rowptr[Nn];
__device__ int    g_woff[Nn];
__device__ int    g_bsum[NB], g_boff[NB];
__device__ int    g_csrc[Ee];
__device__ int    g_is64;
// preconverted transposed weights: [n][k], bf16 hi/lo
__device__ __align__(16) __nv_bfloat16 g_Wt1_hi[128 * 128], g_Wt1_lo[128 * 128];
__device__ __align__(16) __nv_bfloat16 g_Wt2_hi[64 * 128],  g_Wt2_lo[64 * 128];

// ---------------- helpers ---------------------------------------------------
__device__ __forceinline__ float lrelu(float x) { return x > 0.f ? x : NEG_SLOPE * x; }

__device__ __forceinline__ void mma_bf16(float c[4], uint32_t a0, uint32_t a1,
                                         uint32_t a2, uint32_t a3,
                                         uint32_t b0, uint32_t b1) {
    asm volatile("mma.sync.aligned.m16n8k16.row.col.f32.bf16.bf16.f32 "
                 "{%0,%1,%2,%3}, {%4,%5,%6,%7}, {%8,%9}, {%0,%1,%2,%3};"
                 : "+f"(c[0]), "+f"(c[1]), "+f"(c[2]), "+f"(c[3])
                 : "r"(a0), "r"(a1), "r"(a2), "r"(a3), "r"(b0), "r"(b1));
}

// ---------------- dtype detection (parallel) ---------------------------------
__global__ void k_detect(const unsigned int* __restrict__ w) {
    __shared__ int bad;
    if (threadIdx.x == 0) bad = 0;
    __syncthreads();
    for (int j = threadIdx.x; j < 1024; j += 256)
        if (w[1 + 2 * j] != 0u) bad = 1;
    __syncthreads();
    if (threadIdx.x == 0) g_is64 = !bad;
}

// fused convert + histogram (g_cnt pre-zeroed via memsetAsync)
__global__ void k_convert_hist(const int* __restrict__ ei) {
    int i = blockIdx.x * blockDim.x + threadIdx.x;
    if (i >= Ee) return;
    int s, d;
    if (g_is64) { s = ei[2 * i]; d = ei[2 * (Ee + i)]; }
    else        { s = ei[i];     d = ei[Ee + i]; }
    s = min(max(s, 0), Nn - 1);
    d = min(max(d, 0), Nn - 1);
    g_src[i] = s;
    g_dst[i] = d;
    atomicAdd(&g_cnt[d], 1);
}

// ---------------- CSR build --------------------------------------------------
__global__ void k_scan_block() {
    __shared__ int sh[1024];
    int t = threadIdx.x;
    int idx = blockIdx.x * 1024 + t;
    int v = (idx < Nn) ? g_cnt[idx] : 0;
    sh[t] = v;
    __syncthreads();
    for (int o = 1; o < 1024; o <<= 1) {
        int add = (t >= o) ? sh[t - o] : 0;
        __syncthreads();
        sh[t] += add;
        __syncthreads();
    }
    if (idx < Nn) g_rowptr[idx] = sh[t] - v;
    if (t == 1023) g_bsum[blockIdx.x] = sh[1023];
}

__global__ void k_scan_top() {
    if (threadIdx.x == 0 && blockIdx.x == 0) {
        int run = 0;
        for (int b = 0; b < NB; b++) { g_boff[b] = run; run += g_bsum[b]; }
    }
}

__global__ void k_scan_add() {
    int i = blockIdx.x * blockDim.x + threadIdx.x;
    if (i >= Nn) return;
    int r = g_rowptr[i] + g_boff[i >> 10];
    g_rowptr[i] = r;
    g_woff[i] = r;
}

__global__ void k_fill() {
    int i = blockIdx.x * blockDim.x + threadIdx.x;
    if (i >= Ee) return;
    int d = g_dst[i];
    int pos = atomicAdd(&g_woff[d], 1);
    g_csrc[pos] = g_src[i];
}

// ---------------- weight preconversion (transposed bf16 hi/lo) ---------------
__global__ void k_prepW(const float* __restrict__ W1, const float* __restrict__ W2) {
    int i = blockIdx.x * blockDim.x + threadIdx.x;
    if (i < 128 * 128) {
        int k = i >> 7, n = i & 127;
        float v = W1[i];
        __nv_bfloat16 hi = __float2bfloat16(v);
        g_Wt1_hi[n * 128 + k] = hi;
        g_Wt1_lo[n * 128 + k] = __float2bfloat16(v - __bfloat162float(hi));
    }
    if (i < 128 * 64) {
        int k = i / 64, n = i % 64;
        float v = W2[i];
        __nv_bfloat16 hi = __float2bfloat16(v);
        g_Wt2_hi[n * 128 + k] = hi;
        g_Wt2_lo[n * 128 + k] = __float2bfloat16(v - __bfloat162float(hi));
    }
}

// ---------------- bf16 split-K tensor-core GEMM ------------------------------
// C[M,BN] = A[M,128] @ B[128,BN], 3-pass bf16 split (hi*hi + hi*lo + lo*hi).
// B comes preconverted/transposed from global: Bt_[n*128 + k].
template<int BN>
__global__ void __launch_bounds__(256, 2)
gemm_tc(const float* __restrict__ A,
        const __nv_bfloat16* __restrict__ Bt_hi,
        const __nv_bfloat16* __restrict__ Bt_lo,
        float* __restrict__ C, int M) {
    constexpr int K  = 128;
    constexpr int BK = 32;
    constexpr int AP = 40;             // padded row (bf16 elems), conflict-free
    constexpr int NBW = BN / 16;

    __shared__ __nv_bfloat16 As_hi[128 * AP], As_lo[128 * AP];
    __shared__ __nv_bfloat16 Bs_hi[BN * AP],  Bs_lo[BN * AP];

    const int tid  = threadIdx.x;
    const int w    = tid >> 5;
    const int lane = tid & 31;
    const int g    = lane >> 2;
    const int q    = lane & 3;
    const int wrow = (w >> 1) * 32;
    const int n0w  = (w & 1) * (BN / 2);
    const int row0 = blockIdx.x * 128;

    float c[2][NBW][4];
#pragma unroll
    for (int m = 0; m < 2; m++)
#pragma unroll
        for (int nb = 0; nb < NBW; nb++)
#pragma unroll
            for (int j = 0; j < 4; j++) c[m][nb][j] = 0.f;

    for (int kt = 0; kt < K; kt += BK) {
        __syncthreads();
        // A tile: 128 rows x 32 k, packed bfloat162 smem stores
#pragma unroll
        for (int it = 0; it < 4; it++) {
            int i = tid + it * 256;
            int row = i >> 3, kq = i & 7;
            int gr = row0 + row;
            float4 v = make_float4(0.f, 0.f, 0.f, 0.f);
            if (gr < M) v = *(const float4*)(A + (size_t)gr * K + kt + kq * 4);
            int base = row * AP + kq * 4;
            __nv_bfloat16 h0 = __float2bfloat16(v.x), h1b = __float2bfloat16(v.y);
            __nv_bfloat16 h2 = __float2bfloat16(v.z), h3 = __float2bfloat16(v.w);
            *(__nv_bfloat162*)&As_hi[base]     = __nv_bfloat162(h0, h1b);
            *(__nv_bfloat162*)&As_hi[base + 2] = __nv_bfloat162(h2, h3);
            *(__nv_bfloat162*)&As_lo[base] = __nv_bfloat162(
                __float2bfloat16(v.x - __bfloat162float(h0)),
                __float2bfloat16(v.y - __bfloat162float(h1b)));
            *(__nv_bfloat162*)&As_lo[base + 2] = __nv_bfloat162(
                __float2bfloat16(v.z - __bfloat162float(h2)),
                __float2bfloat16(v.w - __bfloat162float(h3)));
        }
        // B tile: BN rows x 32 k, pure uint4 copies from preconverted global
#pragma unroll
        for (int it = 0; it < BN * 4 / 256; it++) {
            int i = tid + it * 256;
            int n = i >> 2, j = i & 3;
            *(uint4*)&Bs_hi[n * AP + j * 8] =
                *(const uint4*)&Bt_hi[n * 128 + kt + j * 8];
            *(uint4*)&Bs_lo[n * AP + j * 8] =
                *(const uint4*)&Bt_lo[n * 128 + kt + j * 8];
        }
        __syncthreads();

#pragma unroll
        for (int kk = 0; kk < BK; kk += 16) {
            uint32_t ahi[2][4], alo[2][4];
#pragma unroll
            for (int m = 0; m < 2; m++) {
                int rb = (wrow + m * 16 + g) * AP + kk + 2 * q;
                ahi[m][0] = *(const uint32_t*)&As_hi[rb];
                ahi[m][1] = *(const uint32_t*)&As_hi[rb + 8 * AP];
                ahi[m][2] = *(const uint32_t*)&As_hi[rb + 8];
                ahi[m][3] = *(const uint32_t*)&As_hi[rb + 8 * AP + 8];
                alo[m][0] = *(const uint32_t*)&As_lo[rb];
                alo[m][1] = *(const uint32_t*)&As_lo[rb + 8 * AP];
                alo[m][2] = *(const uint32_t*)&As_lo[rb + 8];
                alo[m][3] = *(const uint32_t*)&As_lo[rb + 8 * AP + 8];
            }
#pragma unroll
            for (int nb = 0; nb < NBW; nb++) {
                int bb = (n0w + nb * 8 + g) * AP + kk + 2 * q;
                uint32_t bh0 = *(const uint32_t*)&Bs_hi[bb];
                uint32_t bh1 = *(const uint32_t*)&Bs_hi[bb + 8];
                uint32_t bl0 = *(const uint32_t*)&Bs_lo[bb];
                uint32_t bl1 = *(const uint32_t*)&Bs_lo[bb + 8];
#pragma unroll
                for (int m = 0; m < 2; m++) {
                    mma_bf16(c[m][nb], ahi[m][0], ahi[m][1], ahi[m][2], ahi[m][3], bh0, bh1);
                    mma_bf16(c[m][nb], ahi[m][0], ahi[m][1], ahi[m][2], ahi[m][3], bl0, bl1);
                    mma_bf16(c[m][nb], alo[m][0], alo[m][1], alo[m][2], alo[m][3], bh0, bh1);
                }
            }
        }
    }

#pragma unroll
    for (int m = 0; m < 2; m++) {
#pragma unroll
        for (int nb = 0; nb < NBW; nb++) {
            int row = row0 + wrow + m * 16 + g;
            int col = n0w + nb * 8 + 2 * q;
            if (row < M)
                *(float2*)(C + (size_t)row * BN + col) = make_float2(c[m][nb][0], c[m][nb][1]);
            if (row + 8 < M)
                *(float2*)(C + (size_t)(row + 8) * BN + col) = make_float2(c[m][nb][2], c[m][nb][3]);
        }
    }
}

// ---------------- per-node attention scores ---------------------------------
__global__ void escore1_k(const float* __restrict__ a_src, const float* __restrict__ a_dst) {
    int w = (blockIdx.x * blockDim.x + threadIdx.x) >> 5;
    int l = threadIdx.x & 31;
    if (w >= Nn) return;
    const float* row = g_h1 + (size_t)w * F1;
    float es[4], ed[4];
#pragma unroll
    for (int j = 0; j < 4; j++) {
        float v = row[j * 32 + l];
        es[j] = v * a_src[j * 32 + l];
        ed[j] = v * a_dst[j * 32 + l];
    }
#pragma unroll
    for (int o = 16; o; o >>= 1) {
#pragma unroll
        for (int j = 0; j < 4; j++) {
            es[j] += __shfl_xor_sync(0xffffffff, es[j], o);
            ed[j] += __shfl_xor_sync(0xffffffff, ed[j], o);
        }
    }
    if (l == 0) {
        g_es1[w] = make_float4(es[0], es[1], es[2], es[3]);
        g_ed1[w] = make_float4(ed[0], ed[1], ed[2], ed[3]);
    }
}

__global__ void escore2_k(const float* __restrict__ a_src, const float* __restrict__ a_dst) {
    int w = (blockIdx.x * blockDim.x + threadIdx.x) >> 5;
    int l = threadIdx.x & 31;
    if (w >= Nn) return;
    const float* row = g_h2 + (size_t)w * OUTF;
    float v0 = row[l], v1 = row[32 + l];
    float es = v0 * a_src[l] + v1 * a_src[32 + l];
    float ed = v0 * a_dst[l] + v1 * a_dst[32 + l];
#pragma unroll
    for (int o = 16; o; o >>= 1) {
        es += __shfl_xor_sync(0xffffffff, es, o);
        ed += __shfl_xor_sync(0xffffffff, ed, o);
    }
    if (l == 0) { g_es2[w] = es; g_ed2[w] = ed; }
}

// ---------------- gather-based message passes (CSR, no atomics) --------------
__global__ void msg1_k(const float* __restrict__ b1) {
    int d = (blockIdx.x * blockDim.x + threadIdx.x) >> 5;
    int l = threadIdx.x & 31;
    if (d >= Nn) return;
    int h = l >> 3;
    const float* es = (const float*)g_es1;
    float edh = ((const float*)&g_ed1[d])[h];
    int start = g_rowptr[d];
    int cnt = g_cnt[d];

    float4 acc = make_float4(0.f, 0.f, 0.f, 0.f);
    float den = 0.f;
    {
        float w = __expf(lrelu(es[4 * d + h] + edh));
        float4 v = ((const float4*)(g_h1 + (size_t)d * F1))[l];
        acc.x = w * v.x; acc.y = w * v.y; acc.z = w * v.z; acc.w = w * v.w;
        den = w;
    }
    for (int e = start; e < start + cnt; e++) {
        int s = g_csrc[e];
        float w = __expf(lrelu(es[4 * s + h] + edh));
        float4 v = ((const float4*)(g_h1 + (size_t)s * F1))[l];
        acc.x += w * v.x; acc.y += w * v.y; acc.z += w * v.z; acc.w += w * v.w;
        den += w;
    }
    float inv = 1.f / (den + 1e-16f);
    const float4 bb = ((const float4*)b1)[l];
    float4 o;
    o.x = acc.x * inv + bb.x;
    o.y = acc.y * inv + bb.y;
    o.z = acc.z * inv + bb.z;
    o.w = acc.w * inv + bb.w;
    o.x = o.x > 0.f ? o.x : expm1f(o.x);
    o.y = o.y > 0.f ? o.y : expm1f(o.y);
    o.z = o.z > 0.f ? o.z : expm1f(o.z);
    o.w = o.w > 0.f ? o.w : expm1f(o.w);
    ((float4*)(g_agg1 + (size_t)d * F1))[l] = o;
}

__global__ void msg2_k(float* __restrict__ out, const float* __restrict__ b2) {
    int d = (blockIdx.x * blockDim.x + threadIdx.x) >> 5;
    int l = threadIdx.x & 31;
    if (d >= Nn) return;
    float edh = g_ed2[d];
    int start = g_rowptr[d];
    int cnt = g_cnt[d];

    float2 acc;
    float den;
    {
        float w = __expf(lrelu(g_es2[d] + edh));
        float2 v = ((const float2*)(g_h2 + (size_t)d * OUTF))[l];
        acc.x = w * v.x; acc.y = w * v.y;
        den = w;
    }
    for (int e = start; e < start + cnt; e++) {
        int s = g_csrc[e];
        float w = __expf(lrelu(g_es2[s] + edh));
        float2 v = ((const float2*)(g_h2 + (size_t)s * OUTF))[l];
        acc.x += w * v.x; acc.y += w * v.y;
        den += w;
    }
    float inv = 1.f / (den + 1e-16f);
    const float2 bb = ((const float2*)b2)[l];
    float2 o;
    o.x = acc.x * inv + bb.x;
    o.y = acc.y * inv + bb.y;
    ((float2*)(out + (size_t)d * OUTF))[l] = o;
}

// ---------------- launch ----------------------------------------------------
extern "C" void kernel_launch(void* const* d_in, const int* in_sizes, int n_in,
                              void* d_out, int out_size) {
    const float* x   = (const float*)d_in[0];
    const int*   ei  = (const int*)d_in[1];
    const float* W1  = (const float*)d_in[2];
    const float* as1 = (const float*)d_in[3];
    const float* ad1 = (const float*)d_in[4];
    const float* b1  = (const float*)d_in[5];
    const float* W2  = (const float*)d_in[6];
    const float* as2 = (const float*)d_in[7];
    const float* ad2 = (const float*)d_in[8];
    const float* b2  = (const float*)d_in[9];
    float* out = (float*)d_out;

    static cudaStream_t s1;
    static cudaEvent_t ev0, ev1;
    static bool inited = false;
    static float *p_h1, *p_agg1, *p_h2;
    static __nv_bfloat16 *pW1h, *pW1l, *pW2h, *pW2l;
    static int *p_cnt;
    if (!inited) {
        cudaStreamCreateWithFlags(&s1, cudaStreamNonBlocking);
        cudaEventCreateWithFlags(&ev0, cudaEventDisableTiming);
        cudaEventCreateWithFlags(&ev1, cudaEventDisableTiming);
        cudaGetSymbolAddress((void**)&p_h1,   g_h1);
        cudaGetSymbolAddress((void**)&p_agg1, g_agg1);
        cudaGetSymbolAddress((void**)&p_h2,   g_h2);
        cudaGetSymbolAddress((void**)&pW1h,   g_Wt1_hi);
        cudaGetSymbolAddress((void**)&pW1l,   g_Wt1_lo);
        cudaGetSymbolAddress((void**)&pW2h,   g_Wt2_hi);
        cudaGetSymbolAddress((void**)&pW2l,   g_Wt2_lo);
        cudaGetSymbolAddress((void**)&p_cnt,  g_cnt);
        inited = true;
    }

    // fork: CSR build chain on s1, concurrent with GEMM1 path on stream 0
    cudaEventRecord(ev0, 0);
    cudaStreamWaitEvent(s1, ev0, 0);

    k_detect<<<1, 256, 0, s1>>>((const unsigned int*)ei);
    cudaMemsetAsync(p_cnt, 0, Nn * sizeof(int), s1);
    k_convert_hist<<<(Ee + 255) / 256, 256, 0, s1>>>(ei);
    k_scan_block<<<NB, 1024, 0, s1>>>();
    k_scan_top<<<1, 32, 0, s1>>>();
    k_scan_add<<<(Nn + 255) / 256, 256, 0, s1>>>();
    k_fill<<<(Ee + 255) / 256, 256, 0, s1>>>();

    // stream 0: weights prep + layer-1 GEMM + scores
    k_prepW<<<(128 * 128 + 255) / 256, 256>>>(W1, W2);
    gemm_tc<128><<<(Nn + 127) / 128, 256>>>(x, pW1h, pW1l, p_h1, Nn);
    escore1_k<<<(Nn * 32 + 255) / 256, 256>>>(as1, ad1);

    // join: msg1 needs CSR
    cudaEventRecord(ev1, s1);
    cudaStreamWaitEvent(0, ev1, 0);

    msg1_k<<<(Nn * 32 + 255) / 256, 256>>>(b1);

    // layer 2
    gemm_tc<64><<<(Nn + 127) / 128, 256>>>(p_agg1, pW2h, pW2l, p_h2, Nn);
    escore2_k<<<(Nn * 32 + 255) / 256, 256>>>(as2, ad2);
    msg2_k<<<(Nn * 32 + 255) / 256, 256>>>(out, b2);
}

// round 7
// speedup vs baseline: 3.0458x; 1.1586x over previous
#include <cuda_runtime.h>
#include <cuda_bf16.h>
#include <cstdint>

#define Nn   100000
#define Ee   1600000
#define F1   128                // HEADS*HID
#define OUTF 64
#define NEG_SLOPE 0.2f
#define NB   ((Nn + 1023) / 1024)   // scan blocks

// ---------------- scratch (static device globals; no allocation) ------------
__device__ __align__(16) float  g_h1[Nn * F1];
__device__ __align__(16) float  g_agg1[Nn * F1];
__device__ __align__(16) float  g_h2[Nn * OUTF];
__device__ float4 g_es1[Nn], g_ed1[Nn];
__device__ float  g_es2[Nn], g_ed2[Nn];
__device__ int    g_src[Ee], g_dst[Ee];
__device__ int    g_cnt[Nn];
__device__ int    g_rowptr[Nn];
__device__ int    g_woff[Nn];
__device__ int    g_bsum[NB], g_boff[NB];
__device__ int    g_csrc[Ee];
__device__ int    g_is64;
__device__ __align__(16) __nv_bfloat16 g_Wt1_hi[128 * 128], g_Wt1_lo[128 * 128];
__device__ __align__(16) __nv_bfloat16 g_Wt2_hi[64 * 128],  g_Wt2_lo[64 * 128];

// ---------------- helpers ---------------------------------------------------
__device__ __forceinline__ float lrelu(float x) { return x > 0.f ? x : NEG_SLOPE * x; }

__device__ __forceinline__ void mma_bf16(float c[4], uint32_t a0, uint32_t a1,
                                         uint32_t a2, uint32_t a3,
                                         uint32_t b0, uint32_t b1) {
    asm volatile("mma.sync.aligned.m16n8k16.row.col.f32.bf16.bf16.f32 "
                 "{%0,%1,%2,%3}, {%4,%5,%6,%7}, {%8,%9}, {%0,%1,%2,%3};"
                 : "+f"(c[0]), "+f"(c[1]), "+f"(c[2]), "+f"(c[3])
                 : "r"(a0), "r"(a1), "r"(a2), "r"(a3), "r"(b0), "r"(b1));
}

// ---------------- dtype detection (parallel) ---------------------------------
__global__ void k_detect(const unsigned int* __restrict__ w) {
    __shared__ int bad;
    if (threadIdx.x == 0) bad = 0;
    __syncthreads();
    for (int j = threadIdx.x; j < 1024; j += 256)
        if (w[1 + 2 * j] != 0u) bad = 1;
    __syncthreads();
    if (threadIdx.x == 0) g_is64 = !bad;
}

__global__ void k_convert_hist(const int* __restrict__ ei) {
    int i = blockIdx.x * blockDim.x + threadIdx.x;
    if (i >= Ee) return;
    int s, d;
    if (g_is64) { s = ei[2 * i]; d = ei[2 * (Ee + i)]; }
    else        { s = ei[i];     d = ei[Ee + i]; }
    s = min(max(s, 0), Nn - 1);
    d = min(max(d, 0), Nn - 1);
    g_src[i] = s;
    g_dst[i] = d;
    atomicAdd(&g_cnt[d], 1);
}

// ---------------- CSR build --------------------------------------------------
__global__ void k_scan_block() {
    __shared__ int sh[1024];
    int t = threadIdx.x;
    int idx = blockIdx.x * 1024 + t;
    int v = (idx < Nn) ? g_cnt[idx] : 0;
    sh[t] = v;
    __syncthreads();
    for (int o = 1; o < 1024; o <<= 1) {
        int add = (t >= o) ? sh[t - o] : 0;
        __syncthreads();
        sh[t] += add;
        __syncthreads();
    }
    if (idx < Nn) g_rowptr[idx] = sh[t] - v;
    if (t == 1023) g_bsum[blockIdx.x] = sh[1023];
}

__global__ void k_scan_top() {          // 1 block x 128 threads, NB <= 128
    int t = threadIdx.x;
    int lane = t & 31, w = t >> 5;
    int v = (t < NB) ? g_bsum[t] : 0;
    int x = v;
#pragma unroll
    for (int o = 1; o < 32; o <<= 1) {
        int y = __shfl_up_sync(0xffffffff, x, o);
        if (lane >= o) x += y;
    }
    __shared__ int ws[4];
    if (lane == 31) ws[w] = x;
    __syncthreads();
    int add = 0;
    for (int i = 0; i < w; i++) add += ws[i];
    if (t < NB) g_boff[t] = x + add - v;   // exclusive
}

__global__ void k_scan_add() {
    int i = blockIdx.x * blockDim.x + threadIdx.x;
    if (i >= Nn) return;
    int r = g_rowptr[i] + g_boff[i >> 10];
    g_rowptr[i] = r;
    g_woff[i] = r;
}

__global__ void k_fill() {
    int i = blockIdx.x * blockDim.x + threadIdx.x;
    if (i >= Ee) return;
    int d = g_dst[i];
    int pos = atomicAdd(&g_woff[d], 1);
    g_csrc[pos] = g_src[i];
}

// ---------------- weight preconversion (transposed bf16 hi/lo) ---------------
__global__ void k_prepW(const float* __restrict__ W1, const float* __restrict__ W2) {
    int i = blockIdx.x * blockDim.x + threadIdx.x;
    if (i < 128 * 128) {
        int k = i >> 7, n = i & 127;
        float v = W1[i];
        __nv_bfloat16 hi = __float2bfloat16(v);
        g_Wt1_hi[n * 128 + k] = hi;
        g_Wt1_lo[n * 128 + k] = __float2bfloat16(v - __bfloat162float(hi));
    }
    if (i < 128 * 64) {
        int k = i / 64, n = i % 64;
        float v = W2[i];
        __nv_bfloat16 hi = __float2bfloat16(v);
        g_Wt2_hi[n * 128 + k] = hi;
        g_Wt2_lo[n * 128 + k] = __float2bfloat16(v - __bfloat162float(hi));
    }
}

// ---------------- bf16 split-K TC GEMM with fused attention scores -----------
// C[M,BN] = A[M,128] @ B[128,BN]; epilogue also computes
// es[row][h] = sum_col C*a_src[col], ed likewise, from register fragments.
// NH=4 (BN=128): warp col-halves own disjoint heads. NH=1 (BN=64): smem combine.
template<int BN, int NH>
__global__ void __launch_bounds__(256, 2)
gemm_tc(const float* __restrict__ A,
        const __nv_bfloat16* __restrict__ Bt_hi,
        const __nv_bfloat16* __restrict__ Bt_lo,
        float* __restrict__ C, int M,
        const float* __restrict__ a_src, const float* __restrict__ a_dst,
        float* __restrict__ es_out, float* __restrict__ ed_out) {
    constexpr int K  = 128;
    constexpr int BK = 32;
    constexpr int AP = 40;
    constexpr int NBW = BN / 16;

    __shared__ __nv_bfloat16 As_hi[128 * AP], As_lo[128 * AP];
    __shared__ __nv_bfloat16 Bs_hi[BN * AP],  Bs_lo[BN * AP];
    __shared__ float sm_es[128], sm_ed[128];   // for NH==1 cross-warp combine

    const int tid  = threadIdx.x;
    const int w    = tid >> 5;
    const int lane = tid & 31;
    const int g    = lane >> 2;
    const int q    = lane & 3;
    const int wrow = (w >> 1) * 32;
    const int n0w  = (w & 1) * (BN / 2);
    const int row0 = blockIdx.x * 128;

    float c[2][NBW][4];
#pragma unroll
    for (int m = 0; m < 2; m++)
#pragma unroll
        for (int nb = 0; nb < NBW; nb++)
#pragma unroll
            for (int j = 0; j < 4; j++) c[m][nb][j] = 0.f;

    for (int kt = 0; kt < K; kt += BK) {
        __syncthreads();
#pragma unroll
        for (int it = 0; it < 4; it++) {
            int i = tid + it * 256;
            int row = i >> 3, kq = i & 7;
            int gr = row0 + row;
            float4 v = make_float4(0.f, 0.f, 0.f, 0.f);
            if (gr < M) v = *(const float4*)(A + (size_t)gr * K + kt + kq * 4);
            int base = row * AP + kq * 4;
            __nv_bfloat16 h0 = __float2bfloat16(v.x), h1b = __float2bfloat16(v.y);
            __nv_bfloat16 h2 = __float2bfloat16(v.z), h3 = __float2bfloat16(v.w);
            *(__nv_bfloat162*)&As_hi[base]     = __nv_bfloat162(h0, h1b);
            *(__nv_bfloat162*)&As_hi[base + 2] = __nv_bfloat162(h2, h3);
            *(__nv_bfloat162*)&As_lo[base] = __nv_bfloat162(
                __float2bfloat16(v.x - __bfloat162float(h0)),
                __float2bfloat16(v.y - __bfloat162float(h1b)));
            *(__nv_bfloat162*)&As_lo[base + 2] = __nv_bfloat162(
                __float2bfloat16(v.z - __bfloat162float(h2)),
                __float2bfloat16(v.w - __bfloat162float(h3)));
        }
#pragma unroll
        for (int it = 0; it < BN * 4 / 256; it++) {
            int i = tid + it * 256;
            int n = i >> 2, j = i & 3;
            *(uint4*)&Bs_hi[n * AP + j * 8] =
                *(const uint4*)&Bt_hi[n * 128 + kt + j * 8];
            *(uint4*)&Bs_lo[n * AP + j * 8] =
                *(const uint4*)&Bt_lo[n * 128 + kt + j * 8];
        }
        __syncthreads();

#pragma unroll
        for (int kk = 0; kk < BK; kk += 16) {
            uint32_t ahi[2][4], alo[2][4];
#pragma unroll
            for (int m = 0; m < 2; m++) {
                int rb = (wrow + m * 16 + g) * AP + kk + 2 * q;
                ahi[m][0] = *(const uint32_t*)&As_hi[rb];
                ahi[m][1] = *(const uint32_t*)&As_hi[rb + 8 * AP];
                ahi[m][2] = *(const uint32_t*)&As_hi[rb + 8];
                ahi[m][3] = *(const uint32_t*)&As_hi[rb + 8 * AP + 8];
                alo[m][0] = *(const uint32_t*)&As_lo[rb];
                alo[m][1] = *(const uint32_t*)&As_lo[rb + 8 * AP];
                alo[m][2] = *(const uint32_t*)&As_lo[rb + 8];
                alo[m][3] = *(const uint32_t*)&As_lo[rb + 8 * AP + 8];
            }
#pragma unroll
            for (int nb = 0; nb < NBW; nb++) {
                int bb = (n0w + nb * 8 + g) * AP + kk + 2 * q;
                uint32_t bh0 = *(const uint32_t*)&Bs_hi[bb];
                uint32_t bh1 = *(const uint32_t*)&Bs_hi[bb + 8];
                uint32_t bl0 = *(const uint32_t*)&Bs_lo[bb];
                uint32_t bl1 = *(const uint32_t*)&Bs_lo[bb + 8];
#pragma unroll
                for (int m = 0; m < 2; m++) {
                    mma_bf16(c[m][nb], ahi[m][0], ahi[m][1], ahi[m][2], ahi[m][3], bh0, bh1);
                    mma_bf16(c[m][nb], ahi[m][0], ahi[m][1], ahi[m][2], ahi[m][3], bl0, bl1);
                    mma_bf16(c[m][nb], alo[m][0], alo[m][1], alo[m][2], alo[m][3], bh0, bh1);
                }
            }
        }
    }

    // ---- C store ----
#pragma unroll
    for (int m = 0; m < 2; m++) {
#pragma unroll
        for (int nb = 0; nb < NBW; nb++) {
            int row = row0 + wrow + m * 16 + g;
            int col = n0w + nb * 8 + 2 * q;
            if (row < M)
                *(float2*)(C + (size_t)row * BN + col) = make_float2(c[m][nb][0], c[m][nb][1]);
            if (row + 8 < M)
                *(float2*)(C + (size_t)(row + 8) * BN + col) = make_float2(c[m][nb][2], c[m][nb][3]);
        }
    }

    // ---- fused score epilogue ----
    constexpr int HW = (NH == 4) ? 2 : 1;     // head slots per warp
    float pes[4][HW], ped[4][HW];
#pragma unroll
    for (int r = 0; r < 4; r++)
#pragma unroll
        for (int hh = 0; hh < HW; hh++) { pes[r][hh] = 0.f; ped[r][hh] = 0.f; }
#pragma unroll
    for (int nb = 0; nb < NBW; nb++) {
        int colg = n0w + nb * 8 + 2 * q;
        float a0s = a_src[colg], a1s = a_src[colg + 1];
        float a0d = a_dst[colg], a1d = a_dst[colg + 1];
        int hh = (NH == 4) ? (nb / (NBW / 2)) : 0;
#pragma unroll
        for (int m = 0; m < 2; m++) {
            pes[m * 2 + 0][hh] += c[m][nb][0] * a0s + c[m][nb][1] * a1s;
            pes[m * 2 + 1][hh] += c[m][nb][2] * a0s + c[m][nb][3] * a1s;
            ped[m * 2 + 0][hh] += c[m][nb][0] * a0d + c[m][nb][1] * a1d;
            ped[m * 2 + 1][hh] += c[m][nb][2] * a0d + c[m][nb][3] * a1d;
        }
    }
    // reduce across q (lanes 4g..4g+3)
#pragma unroll
    for (int r = 0; r < 4; r++)
#pragma unroll
        for (int hh = 0; hh < HW; hh++) {
            pes[r][hh] += __shfl_xor_sync(0xffffffff, pes[r][hh], 1);
            pes[r][hh] += __shfl_xor_sync(0xffffffff, pes[r][hh], 2);
            ped[r][hh] += __shfl_xor_sync(0xffffffff, ped[r][hh], 1);
            ped[r][hh] += __shfl_xor_sync(0xffffffff, ped[r][hh], 2);
        }

    if (NH == 4) {
        // warp col-half owns heads {0,1} (n0w=0) or {2,3} (n0w=64): direct store
        if (q == 0) {
#pragma unroll
            for (int r = 0; r < 4; r++) {
                int row = row0 + wrow + (r >> 1) * 16 + g + (r & 1) * 8;
                if (row < M) {
                    int hb = (n0w / 32);
                    es_out[row * 4 + hb]     = pes[r][0];
                    es_out[row * 4 + hb + 1] = pes[r][1];
                    ed_out[row * 4 + hb]     = ped[r][0];
                    ed_out[row * 4 + hb + 1] = ped[r][1];
                }
            }
        }
    } else {
        // single head: combine the two col-half warps through smem
        if ((w & 1) && q == 0) {
#pragma unroll
            for (int r = 0; r < 4; r++) {
                int lr = wrow + (r >> 1) * 16 + g + (r & 1) * 8;
                sm_es[lr] = pes[r][0];
                sm_ed[lr] = ped[r][0];
            }
        }
        __syncthreads();
        if (!(w & 1) && q == 0) {
#pragma unroll
            for (int r = 0; r < 4; r++) {
                int lr = wrow + (r >> 1) * 16 + g + (r & 1) * 8;
                int row = row0 + lr;
                if (row < M) {
                    es_out[row] = pes[r][0] + sm_es[lr];
                    ed_out[row] = ped[r][0] + sm_ed[lr];
                }
            }
        }
    }
}

// ---------------- gather-based message passes (CSR, no atomics) --------------
__global__ void msg1_k(const float* __restrict__ b1) {
    int d = (blockIdx.x * blockDim.x + threadIdx.x) >> 5;
    int l = threadIdx.x & 31;
    if (d >= Nn) return;
    int h = l >> 3;
    const float* es = (const float*)g_es1;
    float edh = ((const float*)&g_ed1[d])[h];
    int start = g_rowptr[d];
    int end = start + g_cnt[d];

    float4 acc;
    float den;
    {
        float w = __expf(lrelu(es[4 * d + h] + edh));
        float4 v = ((const float4*)(g_h1 + (size_t)d * F1))[l];
        acc.x = w * v.x; acc.y = w * v.y; acc.z = w * v.z; acc.w = w * v.w;
        den = w;
    }
    int e = start;
    for (; e + 1 < end; e += 2) {
        int s0 = g_csrc[e], s1 = g_csrc[e + 1];
        float w0 = __expf(lrelu(es[4 * s0 + h] + edh));
        float w1 = __expf(lrelu(es[4 * s1 + h] + edh));
        float4 v0 = ((const float4*)(g_h1 + (size_t)s0 * F1))[l];
        float4 v1 = ((const float4*)(g_h1 + (size_t)s1 * F1))[l];
        acc.x += w0 * v0.x + w1 * v1.x;
        acc.y += w0 * v0.y + w1 * v1.y;
        acc.z += w0 * v0.z + w1 * v1.z;
        acc.w += w0 * v0.w + w1 * v1.w;
        den += w0 + w1;
    }
    if (e < end) {
        int s = g_csrc[e];
        float w = __expf(lrelu(es[4 * s + h] + edh));
        float4 v = ((const float4*)(g_h1 + (size_t)s * F1))[l];
        acc.x += w * v.x; acc.y += w * v.y; acc.z += w * v.z; acc.w += w * v.w;
        den += w;
    }
    float inv = 1.f / (den + 1e-16f);
    const float4 bb = ((const float4*)b1)[l];
    float4 o;
    o.x = acc.x * inv + bb.x;
    o.y = acc.y * inv + bb.y;
    o.z = acc.z * inv + bb.z;
    o.w = acc.w * inv + bb.w;
    o.x = o.x > 0.f ? o.x : expm1f(o.x);
    o.y = o.y > 0.f ? o.y : expm1f(o.y);
    o.z = o.z > 0.f ? o.z : expm1f(o.z);
    o.w = o.w > 0.f ? o.w : expm1f(o.w);
    ((float4*)(g_agg1 + (size_t)d * F1))[l] = o;
}

__global__ void msg2_k(float* __restrict__ out, const float* __restrict__ b2) {
    int d = (blockIdx.x * blockDim.x + threadIdx.x) >> 5;
    int l = threadIdx.x & 31;
    if (d >= Nn) return;
    float edh = g_ed2[d];
    int start = g_rowptr[d];
    int end = start + g_cnt[d];

    float2 acc;
    float den;
    {
        float w = __expf(lrelu(g_es2[d] + edh));
        float2 v = ((const float2*)(g_h2 + (size_t)d * OUTF))[l];
        acc.x = w * v.x; acc.y = w * v.y;
        den = w;
    }
    int e = start;
    for (; e + 1 < end; e += 2) {
        int s0 = g_csrc[e], s1 = g_csrc[e + 1];
        float w0 = __expf(lrelu(g_es2[s0] + edh));
        float w1 = __expf(lrelu(g_es2[s1] + edh));
        float2 v0 = ((const float2*)(g_h2 + (size_t)s0 * OUTF))[l];
        float2 v1 = ((const float2*)(g_h2 + (size_t)s1 * OUTF))[l];
        acc.x += w0 * v0.x + w1 * v1.x;
        acc.y += w0 * v0.y + w1 * v1.y;
        den += w0 + w1;
    }
    if (e < end) {
        int s = g_csrc[e];
        float w = __expf(lrelu(g_es2[s] + edh));
        float2 v = ((const float2*)(g_h2 + (size_t)s * OUTF))[l];
        acc.x += w * v.x; acc.y += w * v.y;
        den += w;
    }
    float inv = 1.f / (den + 1e-16f);
    const float2 bb = ((const float2*)b2)[l];
    float2 o;
    o.x = acc.x * inv + bb.x;
    o.y = acc.y * inv + bb.y;
    ((float2*)(out + (size_t)d * OUTF))[l] = o;
}

// ---------------- launch ----------------------------------------------------
extern "C" void kernel_launch(void* const* d_in, const int* in_sizes, int n_in,
                              void* d_out, int out_size) {
    const float* x   = (const float*)d_in[0];
    const int*   ei  = (const int*)d_in[1];
    const float* W1  = (const float*)d_in[2];
    const float* as1 = (const float*)d_in[3];
    const float* ad1 = (const float*)d_in[4];
    const float* b1  = (const float*)d_in[5];
    const float* W2  = (const float*)d_in[6];
    const float* as2 = (const float*)d_in[7];
    const float* ad2 = (const float*)d_in[8];
    const float* b2  = (const float*)d_in[9];
    float* out = (float*)d_out;

    static cudaStream_t s1;
    static cudaEvent_t ev0, ev1;
    static bool inited = false;
    static float *p_h1, *p_agg1, *p_h2, *p_es1, *p_ed1, *p_es2, *p_ed2;
    static __nv_bfloat16 *pW1h, *pW1l, *pW2h, *pW2l;
    static int *p_cnt;
    if (!inited) {
        cudaStreamCreateWithFlags(&s1, cudaStreamNonBlocking);
        cudaEventCreateWithFlags(&ev0, cudaEventDisableTiming);
        cudaEventCreateWithFlags(&ev1, cudaEventDisableTiming);
        cudaGetSymbolAddress((void**)&p_h1,   g_h1);
        cudaGetSymbolAddress((void**)&p_agg1, g_agg1);
        cudaGetSymbolAddress((void**)&p_h2,   g_h2);
        cudaGetSymbolAddress((void**)&p_es1,  g_es1);
        cudaGetSymbolAddress((void**)&p_ed1,  g_ed1);
        cudaGetSymbolAddress((void**)&p_es2,  g_es2);
        cudaGetSymbolAddress((void**)&p_ed2,  g_ed2);
        cudaGetSymbolAddress((void**)&pW1h,   g_Wt1_hi);
        cudaGetSymbolAddress((void**)&pW1l,   g_Wt1_lo);
        cudaGetSymbolAddress((void**)&pW2h,   g_Wt2_hi);
        cudaGetSymbolAddress((void**)&pW2l,   g_Wt2_lo);
        cudaGetSymbolAddress((void**)&p_cnt,  g_cnt);
        inited = true;
    }

    // fork: CSR build chain on s1, concurrent with GEMM1 path on stream 0
    cudaEventRecord(ev0, 0);
    cudaStreamWaitEvent(s1, ev0, 0);

    k_detect<<<1, 256, 0, s1>>>((const unsigned int*)ei);
    cudaMemsetAsync(p_cnt, 0, Nn * sizeof(int), s1);
    k_convert_hist<<<(Ee + 255) / 256, 256, 0, s1>>>(ei);
    k_scan_block<<<NB, 1024, 0, s1>>>();
    k_scan_top<<<1, 128, 0, s1>>>();
    k_scan_add<<<(Nn + 255) / 256, 256, 0, s1>>>();
    k_fill<<<(Ee + 255) / 256, 256, 0, s1>>>();

    // stream 0: weights prep + layer-1 GEMM (scores fused)
    k_prepW<<<(128 * 128 + 255) / 256, 256>>>(W1, W2);
    gemm_tc<128, 4><<<(Nn + 127) / 128, 256>>>(x, pW1h, pW1l, p_h1, Nn,
                                               as1, ad1, p_es1, p_ed1);

    // join: msg1 needs CSR
    cudaEventRecord(ev1, s1);
    cudaStreamWaitEvent(0, ev1, 0);

    msg1_k<<<(Nn * 32 + 255) / 256, 256>>>(b1);

    // layer 2 (scores fused)
    gemm_tc<64, 1><<<(Nn + 127) / 128, 256>>>(p_agg1, pW2h, pW2l, p_h2, Nn,
                                              as2, ad2, p_es2, p_ed2);
    msg2_k<<<(Nn * 32 + 255) / 256, 256>>>(out, b2);
}

// round 8
// speedup vs baseline: 3.1220x; 1.0250x over previous
#include <cuda_runtime.h>
#include <cuda_bf16.h>
#include <cstdint>

#define Nn   100000
#define Ee   1600000
#define F1   128                // HEADS*HID
#define OUTF 64
#define NEG_SLOPE 0.2f
#define NB   ((Nn + 1023) / 1024)   // scan blocks

// ---------------- scratch (static device globals; no allocation) ------------
__device__ __align__(16) float  g_h1[Nn * F1];
__device__ __align__(16) float  g_agg1[Nn * F1];
__device__ __align__(16) float  g_h2[Nn * OUTF];
__device__ float4 g_es1[Nn], g_ed1[Nn];
__device__ float  g_es2[Nn], g_ed2[Nn];
__device__ int    g_src[Ee], g_dst[Ee];
__device__ int    g_cnt[Nn];
__device__ int    g_rowptr[Nn];
__device__ int    g_woff[Nn];
__device__ int    g_bsum[NB], g_boff[NB];
__device__ int    g_csrc[Ee];
__device__ int    g_is64;
__device__ __align__(16) __nv_bfloat16 g_Wt1_hi[128 * 128], g_Wt1_lo[128 * 128];
__device__ __align__(16) __nv_bfloat16 g_Wt2_hi[64 * 128],  g_Wt2_lo[64 * 128];

// ---------------- helpers ---------------------------------------------------
__device__ __forceinline__ float lrelu(float x) { return x > 0.f ? x : NEG_SLOPE * x; }

__device__ __forceinline__ void mma_bf16(float c[4], uint32_t a0, uint32_t a1,
                                         uint32_t a2, uint32_t a3,
                                         uint32_t b0, uint32_t b1) {
    asm volatile("mma.sync.aligned.m16n8k16.row.col.f32.bf16.bf16.f32 "
                 "{%0,%1,%2,%3}, {%4,%5,%6,%7}, {%8,%9}, {%0,%1,%2,%3};"
                 : "+f"(c[0]), "+f"(c[1]), "+f"(c[2]), "+f"(c[3])
                 : "r"(a0), "r"(a1), "r"(a2), "r"(a3), "r"(b0), "r"(b1));
}

// ---------------- dtype detection (parallel) ---------------------------------
__global__ void k_detect(const unsigned int* __restrict__ w) {
    __shared__ int bad;
    if (threadIdx.x == 0) bad = 0;
    __syncthreads();
    for (int j = threadIdx.x; j < 1024; j += 256)
        if (w[1 + 2 * j] != 0u) bad = 1;
    __syncthreads();
    if (threadIdx.x == 0) g_is64 = !bad;
}

__global__ void k_convert_hist(const int* __restrict__ ei) {
    int i = blockIdx.x * blockDim.x + threadIdx.x;
    if (i >= Ee) return;
    int s, d;
    if (g_is64) { s = ei[2 * i]; d = ei[2 * (Ee + i)]; }
    else        { s = ei[i];     d = ei[Ee + i]; }
    s = min(max(s, 0), Nn - 1);
    d = min(max(d, 0), Nn - 1);
    g_src[i] = s;
    g_dst[i] = d;
    atomicAdd(&g_cnt[d], 1);
}

// ---------------- CSR build --------------------------------------------------
__global__ void k_scan_block() {
    __shared__ int sh[1024];
    int t = threadIdx.x;
    int idx = blockIdx.x * 1024 + t;
    int v = (idx < Nn) ? g_cnt[idx] : 0;
    sh[t] = v;
    __syncthreads();
    for (int o = 1; o < 1024; o <<= 1) {
        int add = (t >= o) ? sh[t - o] : 0;
        __syncthreads();
        sh[t] += add;
        __syncthreads();
    }
    if (idx < Nn) g_rowptr[idx] = sh[t] - v;
    if (t == 1023) g_bsum[blockIdx.x] = sh[1023];
}

__global__ void k_scan_top() {          // 1 block x 128 threads, NB <= 128
    int t = threadIdx.x;
    int lane = t & 31, w = t >> 5;
    int v = (t < NB) ? g_bsum[t] : 0;
    int x = v;
#pragma unroll
    for (int o = 1; o < 32; o <<= 1) {
        int y = __shfl_up_sync(0xffffffff, x, o);
        if (lane >= o) x += y;
    }
    __shared__ int ws[4];
    if (lane == 31) ws[w] = x;
    __syncthreads();
    int add = 0;
    for (int i = 0; i < w; i++) add += ws[i];
    if (t < NB) g_boff[t] = x + add - v;   // exclusive
}

__global__ void k_scan_add() {
    int i = blockIdx.x * blockDim.x + threadIdx.x;
    if (i >= Nn) return;
    int r = g_rowptr[i] + g_boff[i >> 10];
    g_rowptr[i] = r;
    g_woff[i] = r;
}

__global__ void k_fill() {
    int i = blockIdx.x * blockDim.x + threadIdx.x;
    if (i >= Ee) return;
    int d = g_dst[i];
    int pos = atomicAdd(&g_woff[d], 1);
    g_csrc[pos] = g_src[i];
}

// ---------------- weight preconversion (transposed bf16 hi/lo) ---------------
__global__ void k_prepW(const float* __restrict__ W1, const float* __restrict__ W2) {
    int i = blockIdx.x * blockDim.x + threadIdx.x;
    if (i < 128 * 128) {
        int k = i >> 7, n = i & 127;
        float v = W1[i];
        __nv_bfloat16 hi = __float2bfloat16(v);
        g_Wt1_hi[n * 128 + k] = hi;
        g_Wt1_lo[n * 128 + k] = __float2bfloat16(v - __bfloat162float(hi));
    }
    if (i < 128 * 64) {
        int k = i / 64, n = i % 64;
        float v = W2[i];
        __nv_bfloat16 hi = __float2bfloat16(v);
        g_Wt2_hi[n * 128 + k] = hi;
        g_Wt2_lo[n * 128 + k] = __float2bfloat16(v - __bfloat162float(hi));
    }
}

// ---------------- bf16 split-K TC GEMM with fused attention scores -----------
// C[M,BN] = A[M,128] @ B[128,BN]; epilogue also computes
// es[row][h] = sum_col C*a_src[col], ed likewise, from register fragments.
// NH=4 (BN=128): warp col-halves own disjoint heads. NH=1 (BN=64): smem combine.
template<int BN, int NH>
__global__ void __launch_bounds__(256, 2)
gemm_tc(const float* __restrict__ A,
        const __nv_bfloat16* __restrict__ Bt_hi,
        const __nv_bfloat16* __restrict__ Bt_lo,
        float* __restrict__ C, int M,
        const float* __restrict__ a_src, const float* __restrict__ a_dst,
        float* __restrict__ es_out, float* __restrict__ ed_out) {
    constexpr int K  = 128;
    constexpr int BK = 32;
    constexpr int AP = 40;
    constexpr int NBW = BN / 16;

    __shared__ __nv_bfloat16 As_hi[128 * AP], As_lo[128 * AP];
    __shared__ __nv_bfloat16 Bs_hi[BN * AP],  Bs_lo[BN * AP];
    __shared__ float sm_es[128], sm_ed[128];   // for NH==1 cross-warp combine

    const int tid  = threadIdx.x;
    const int w    = tid >> 5;
    const int lane = tid & 31;
    const int g    = lane >> 2;
    const int q    = lane & 3;
    const int wrow = (w >> 1) * 32;
    const int n0w  = (w & 1) * (BN / 2);
    const int row0 = blockIdx.x * 128;

    float c[2][NBW][4];
#pragma unroll
    for (int m = 0; m < 2; m++)
#pragma unroll
        for (int nb = 0; nb < NBW; nb++)
#pragma unroll
            for (int j = 0; j < 4; j++) c[m][nb][j] = 0.f;

    for (int kt = 0; kt < K; kt += BK) {
        __syncthreads();
#pragma unroll
        for (int it = 0; it < 4; it++) {
            int i = tid + it * 256;
            int row = i >> 3, kq = i & 7;
            int gr = row0 + row;
            float4 v = make_float4(0.f, 0.f, 0.f, 0.f);
            if (gr < M) v = *(const float4*)(A + (size_t)gr * K + kt + kq * 4);
            int base = row * AP + kq * 4;
            __nv_bfloat16 h0 = __float2bfloat16(v.x), h1b = __float2bfloat16(v.y);
            __nv_bfloat16 h2 = __float2bfloat16(v.z), h3 = __float2bfloat16(v.w);
            *(__nv_bfloat162*)&As_hi[base]     = __nv_bfloat162(h0, h1b);
            *(__nv_bfloat162*)&As_hi[base + 2] = __nv_bfloat162(h2, h3);
            *(__nv_bfloat162*)&As_lo[base] = __nv_bfloat162(
                __float2bfloat16(v.x - __bfloat162float(h0)),
                __float2bfloat16(v.y - __bfloat162float(h1b)));
            *(__nv_bfloat162*)&As_lo[base + 2] = __nv_bfloat162(
                __float2bfloat16(v.z - __bfloat162float(h2)),
                __float2bfloat16(v.w - __bfloat162float(h3)));
        }
#pragma unroll
        for (int it = 0; it < BN * 4 / 256; it++) {
            int i = tid + it * 256;
            int n = i >> 2, j = i & 3;
            *(uint4*)&Bs_hi[n * AP + j * 8] =
                *(const uint4*)&Bt_hi[n * 128 + kt + j * 8];
            *(uint4*)&Bs_lo[n * AP + j * 8] =
                *(const uint4*)&Bt_lo[n * 128 + kt + j * 8];
        }
        __syncthreads();

#pragma unroll
        for (int kk = 0; kk < BK; kk += 16) {
            uint32_t ahi[2][4], alo[2][4];
#pragma unroll
            for (int m = 0; m < 2; m++) {
                int rb = (wrow + m * 16 + g) * AP + kk + 2 * q;
                ahi[m][0] = *(const uint32_t*)&As_hi[rb];
                ahi[m][1] = *(const uint32_t*)&As_hi[rb + 8 * AP];
                ahi[m][2] = *(const uint32_t*)&As_hi[rb + 8];
                ahi[m][3] = *(const uint32_t*)&As_hi[rb + 8 * AP + 8];
                alo[m][0] = *(const uint32_t*)&As_lo[rb];
                alo[m][1] = *(const uint32_t*)&As_lo[rb + 8 * AP];
                alo[m][2] = *(const uint32_t*)&As_lo[rb + 8];
                alo[m][3] = *(const uint32_t*)&As_lo[rb + 8 * AP + 8];
            }
#pragma unroll
            for (int nb = 0; nb < NBW; nb++) {
                int bb = (n0w + nb * 8 + g) * AP + kk + 2 * q;
                uint32_t bh0 = *(const uint32_t*)&Bs_hi[bb];
                uint32_t bh1 = *(const uint32_t*)&Bs_hi[bb + 8];
                uint32_t bl0 = *(const uint32_t*)&Bs_lo[bb];
                uint32_t bl1 = *(const uint32_t*)&Bs_lo[bb + 8];
#pragma unroll
                for (int m = 0; m < 2; m++) {
                    mma_bf16(c[m][nb], ahi[m][0], ahi[m][1], ahi[m][2], ahi[m][3], bh0, bh1);
                    mma_bf16(c[m][nb], ahi[m][0], ahi[m][1], ahi[m][2], ahi[m][3], bl0, bl1);
                    mma_bf16(c[m][nb], alo[m][0], alo[m][1], alo[m][2], alo[m][3], bh0, bh1);
                }
            }
        }
    }

    // ---- C store ----
#pragma unroll
    for (int m = 0; m < 2; m++) {
#pragma unroll
        for (int nb = 0; nb < NBW; nb++) {
            int row = row0 + wrow + m * 16 + g;
            int col = n0w + nb * 8 + 2 * q;
            if (row < M)
                *(float2*)(C + (size_t)row * BN + col) = make_float2(c[m][nb][0], c[m][nb][1]);
            if (row + 8 < M)
                *(float2*)(C + (size_t)(row + 8) * BN + col) = make_float2(c[m][nb][2], c[m][nb][3]);
        }
    }

    // ---- fused score epilogue ----
    constexpr int HW = (NH == 4) ? 2 : 1;     // head slots per warp
    float pes[4][HW], ped[4][HW];
#pragma unroll
    for (int r = 0; r < 4; r++)
#pragma unroll
        for (int hh = 0; hh < HW; hh++) { pes[r][hh] = 0.f; ped[r][hh] = 0.f; }
#pragma unroll
    for (int nb = 0; nb < NBW; nb++) {
        int colg = n0w + nb * 8 + 2 * q;
        float a0s = a_src[colg], a1s = a_src[colg + 1];
        float a0d = a_dst[colg], a1d = a_dst[colg + 1];
        int hh = (NH == 4) ? (nb / (NBW / 2)) : 0;
#pragma unroll
        for (int m = 0; m < 2; m++) {
            pes[m * 2 + 0][hh] += c[m][nb][0] * a0s + c[m][nb][1] * a1s;
            pes[m * 2 + 1][hh] += c[m][nb][2] * a0s + c[m][nb][3] * a1s;
            ped[m * 2 + 0][hh] += c[m][nb][0] * a0d + c[m][nb][1] * a1d;
            ped[m * 2 + 1][hh] += c[m][nb][2] * a0d + c[m][nb][3] * a1d;
        }
    }
    // reduce across q (lanes 4g..4g+3)
#pragma unroll
    for (int r = 0; r < 4; r++)
#pragma unroll
        for (int hh = 0; hh < HW; hh++) {
            pes[r][hh] += __shfl_xor_sync(0xffffffff, pes[r][hh], 1);
            pes[r][hh] += __shfl_xor_sync(0xffffffff, pes[r][hh], 2);
            ped[r][hh] += __shfl_xor_sync(0xffffffff, ped[r][hh], 1);
            ped[r][hh] += __shfl_xor_sync(0xffffffff, ped[r][hh], 2);
        }

    if (NH == 4) {
        // warp col-half owns heads {0,1} (n0w=0) or {2,3} (n0w=64): direct store
        if (q == 0) {
#pragma unroll
            for (int r = 0; r < 4; r++) {
                int row = row0 + wrow + (r >> 1) * 16 + g + (r & 1) * 8;
                if (row < M) {
                    int hb = (n0w / 32);
                    es_out[row * 4 + hb]     = pes[r][0];
                    es_out[row * 4 + hb + 1] = pes[r][1];
                    ed_out[row * 4 + hb]     = ped[r][0];
                    ed_out[row * 4 + hb + 1] = ped[r][1];
                }
            }
        }
    } else {
        // single head: combine the two col-half warps through smem
        if ((w & 1) && q == 0) {
#pragma unroll
            for (int r = 0; r < 4; r++) {
                int lr = wrow + (r >> 1) * 16 + g + (r & 1) * 8;
                sm_es[lr] = pes[r][0];
                sm_ed[lr] = ped[r][0];
            }
        }
        __syncthreads();
        if (!(w & 1) && q == 0) {
#pragma unroll
            for (int r = 0; r < 4; r++) {
                int lr = wrow + (r >> 1) * 16 + g + (r & 1) * 8;
                int row = row0 + lr;
                if (row < M) {
                    es_out[row] = pes[r][0] + sm_es[lr];
                    ed_out[row] = ped[r][0] + sm_ed[lr];
                }
            }
        }
    }
}

// ---------------- gather-based message passes (CSR, no atomics) --------------
__global__ void msg1_k(const float* __restrict__ b1) {
    int d = (blockIdx.x * blockDim.x + threadIdx.x) >> 5;
    int l = threadIdx.x & 31;
    if (d >= Nn) return;
    int h = l >> 3;
    const float* es = (const float*)g_es1;
    float edh = ((const float*)&g_ed1[d])[h];
    int start = g_rowptr[d];
    int end = start + g_cnt[d];

    float4 acc;
    float den;
    {
        float w = __expf(lrelu(es[4 * d + h] + edh));
        float4 v = ((const float4*)(g_h1 + (size_t)d * F1))[l];
        acc.x = w * v.x; acc.y = w * v.y; acc.z = w * v.z; acc.w = w * v.w;
        den = w;
    }
    int e = start;
    for (; e + 1 < end; e += 2) {
        int s0 = g_csrc[e], s1 = g_csrc[e + 1];
        float w0 = __expf(lrelu(es[4 * s0 + h] + edh));
        float w1 = __expf(lrelu(es[4 * s1 + h] + edh));
        float4 v0 = ((const float4*)(g_h1 + (size_t)s0 * F1))[l];
        float4 v1 = ((const float4*)(g_h1 + (size_t)s1 * F1))[l];
        acc.x += w0 * v0.x + w1 * v1.x;
        acc.y += w0 * v0.y + w1 * v1.y;
        acc.z += w0 * v0.z + w1 * v1.z;
        acc.w += w0 * v0.w + w1 * v1.w;
        den += w0 + w1;
    }
    if (e < end) {
        int s = g_csrc[e];
        float w = __expf(lrelu(es[4 * s + h] + edh));
        float4 v = ((const float4*)(g_h1 + (size_t)s * F1))[l];
        acc.x += w * v.x; acc.y += w * v.y; acc.z += w * v.z; acc.w += w * v.w;
        den += w;
    }
    float inv = 1.f / (den + 1e-16f);
    const float4 bb = ((const float4*)b1)[l];
    float4 o;
    o.x = acc.x * inv + bb.x;
    o.y = acc.y * inv + bb.y;
    o.z = acc.z * inv + bb.z;
    o.w = acc.w * inv + bb.w;
    o.x = o.x > 0.f ? o.x : expm1f(o.x);
    o.y = o.y > 0.f ? o.y : expm1f(o.y);
    o.z = o.z > 0.f ? o.z : expm1f(o.z);
    o.w = o.w > 0.f ? o.w : expm1f(o.w);
    ((float4*)(g_agg1 + (size_t)d * F1))[l] = o;
}

__global__ void msg2_k(float* __restrict__ out, const float* __restrict__ b2) {
    int d = (blockIdx.x * blockDim.x + threadIdx.x) >> 5;
    int l = threadIdx.x & 31;
    if (d >= Nn) return;
    float edh = g_ed2[d];
    int start = g_rowptr[d];
    int end = start + g_cnt[d];

    float2 acc;
    float den;
    {
        float w = __expf(lrelu(g_es2[d] + edh));
        float2 v = ((const float2*)(g_h2 + (size_t)d * OUTF))[l];
        acc.x = w * v.x; acc.y = w * v.y;
        den = w;
    }
    int e = start;
    for (; e + 1 < end; e += 2) {
        int s0 = g_csrc[e], s1 = g_csrc[e + 1];
        float w0 = __expf(lrelu(g_es2[s0] + edh));
        float w1 = __expf(lrelu(g_es2[s1] + edh));
        float2 v0 = ((const float2*)(g_h2 + (size_t)s0 * OUTF))[l];
        float2 v1 = ((const float2*)(g_h2 + (size_t)s1 * OUTF))[l];
        acc.x += w0 * v0.x + w1 * v1.x;
        acc.y += w0 * v0.y + w1 * v1.y;
        den += w0 + w1;
    }
    if (e < end) {
        int s = g_csrc[e];
        float w = __expf(lrelu(g_es2[s] + edh));
        float2 v = ((const float2*)(g_h2 + (size_t)s * OUTF))[l];
        acc.x += w * v.x; acc.y += w * v.y;
        den += w;
    }
    float inv = 1.f / (den + 1e-16f);
    const float2 bb = ((const float2*)b2)[l];
    float2 o;
    o.x = acc.x * inv + bb.x;
    o.y = acc.y * inv + bb.y;
    ((float2*)(out + (size_t)d * OUTF))[l] = o;
}

// ---------------- launch ----------------------------------------------------
extern "C" void kernel_launch(void* const* d_in, const int* in_sizes, int n_in,
                              void* d_out, int out_size) {
    const float* x   = (const float*)d_in[0];
    const int*   ei  = (const int*)d_in[1];
    const float* W1  = (const float*)d_in[2];
    const float* as1 = (const float*)d_in[3];
    const float* ad1 = (const float*)d_in[4];
    const float* b1  = (const float*)d_in[5];
    const float* W2  = (const float*)d_in[6];
    const float* as2 = (const float*)d_in[7];
    const float* ad2 = (const float*)d_in[8];
    const float* b2  = (const float*)d_in[9];
    float* out = (float*)d_out;

    static cudaStream_t s1;
    static cudaEvent_t ev0, ev1;
    static bool inited = false;
    static float *p_h1, *p_agg1, *p_h2, *p_es1, *p_ed1, *p_es2, *p_ed2;
    static __nv_bfloat16 *pW1h, *pW1l, *pW2h, *pW2l;
    static int *p_cnt;
    if (!inited) {
        cudaStreamCreateWithFlags(&s1, cudaStreamNonBlocking);
        cudaEventCreateWithFlags(&ev0, cudaEventDisableTiming);
        cudaEventCreateWithFlags(&ev1, cudaEventDisableTiming);
        cudaGetSymbolAddress((void**)&p_h1,   g_h1);
        cudaGetSymbolAddress((void**)&p_agg1, g_agg1);
        cudaGetSymbolAddress((void**)&p_h2,   g_h2);
        cudaGetSymbolAddress((void**)&p_es1,  g_es1);
        cudaGetSymbolAddress((void**)&p_ed1,  g_ed1);
        cudaGetSymbolAddress((void**)&p_es2,  g_es2);
        cudaGetSymbolAddress((void**)&p_ed2,  g_ed2);
        cudaGetSymbolAddress((void**)&pW1h,   g_Wt1_hi);
        cudaGetSymbolAddress((void**)&pW1l,   g_Wt1_lo);
        cudaGetSymbolAddress((void**)&pW2h,   g_Wt2_hi);
        cudaGetSymbolAddress((void**)&pW2l,   g_Wt2_lo);
        cudaGetSymbolAddress((void**)&p_cnt,  g_cnt);
        inited = true;
    }

    // fork: CSR build chain on s1, concurrent with GEMM1 path on stream 0
    cudaEventRecord(ev0, 0);
    cudaStreamWaitEvent(s1, ev0, 0);

    k_detect<<<1, 256, 0, s1>>>((const unsigned int*)ei);
    cudaMemsetAsync(p_cnt, 0, Nn * sizeof(int), s1);
    k_convert_hist<<<(Ee + 255) / 256, 256, 0, s1>>>(ei);
    k_scan_block<<<NB, 1024, 0, s1>>>();
    k_scan_top<<<1, 128, 0, s1>>>();
    k_scan_add<<<(Nn + 255) / 256, 256, 0, s1>>>();
    k_fill<<<(Ee + 255) / 256, 256, 0, s1>>>();

    // stream 0: weights prep + layer-1 GEMM (scores fused)
    k_prepW<<<(128 * 128 + 255) / 256, 256>>>(W1, W2);
    gemm_tc<128, 4><<<(Nn + 127) / 128, 256>>>(x, pW1h, pW1l, p_h1, Nn,
                                               as1, ad1, p_es1, p_ed1);

    // join: msg1 needs CSR
    cudaEventRecord(ev1, s1);
    cudaStreamWaitEvent(0, ev1, 0);

    msg1_k<<<(Nn * 32 + 255) / 256, 256>>>(b1);

    // layer 2 (scores fused)
    gemm_tc<64, 1><<<(Nn + 127) / 128, 256>>>(p_agg1, pW2h, pW2l, p_h2, Nn,
                                              as2, ad2, p_es2, p_ed2);
    msg2_k<<<(Nn * 32 + 255) / 256, 256>>>(out, b2);
}